// round 12
// baseline (speedup 1.0000x reference)
#include <cuda_runtime.h>
#include <math.h>

#define BB 32
#define HH 128
#define WW 128
#define CC 64
#define MX 16
#define MY 16
#define NK 17

typedef unsigned long long u64;

__device__ __forceinline__ u64 pk(float a, float b) {
    u64 r; asm("mov.b64 %0, {%1,%2};" : "=l"(r) : "f"(a), "f"(b)); return r;
}
__device__ __forceinline__ float2 upk(u64 v) {
    float2 f; asm("mov.b64 {%0,%1}, %2;" : "=f"(f.x), "=f"(f.y) : "l"(v)); return f;
}
__device__ __forceinline__ void fma2(u64 &d, u64 a, u64 b) {
    asm("fma.rn.f32x2 %0, %1, %2, %0;" : "+l"(d) : "l"(a), "l"(b));
}
__device__ __forceinline__ void add2(u64 &d, u64 a) {
    asm("add.rn.f32x2 %0, %0, %1;" : "+l"(d) : "l"(a));
}
__device__ __forceinline__ float fast_tanh(float x) {
    float t; asm("tanh.approx.f32 %0, %1;" : "=f"(t) : "f"(x)); return t;
}
__device__ __forceinline__ unsigned sptr(const void* p) {
    unsigned a;
    asm("{ .reg .u64 t; cvta.to.shared.u64 t, %1; cvt.u32.u64 %0, t; }" : "=r"(a) : "l"(p));
    return a;
}
#define CP16(s, g) asm volatile("cp.async.cg.shared.global [%0], [%1], 16;" :: "r"(s), "l"(g))

// ---------------- scratch ----------------
__device__ __align__(16) u64 g_X1[BB*NK*WW*CC];        // (re,im)
__device__ __align__(16) u64 g_Y [BB*32*MY*CC];        // (re,im)
__device__ __align__(16) u64 g_G [BB*MY*32*CC];        // (re,im) [b][ky][r][c]
__device__ __align__(16) float g_Mre[BB*MY*HH*CC];
__device__ __align__(16) float g_Mim[BB*MY*HH*CC];

// twiddle tables
__device__ __align__(16) u64 g_TA2[HH*18];             // [h][k] pk(cos,-sin), k=17 pad 0
__device__ __align__(16) u64 g_TBc[WW*MY];             // pk(c,c)
__device__ __align__(16) u64 g_TBs[WW*MY];             // pk(s,s)
__device__ __align__(16) ulonglong2 g_TP[128];         // {pk(c,c), pk(s,s)}
__device__ __align__(16) u64 g_TC2[WW*8];
__device__ __align__(16) u64 g_TS2[WW*8];

// ---------------- init ----------------
__global__ void k_init() {
    int t = blockIdx.x * blockDim.x + threadIdx.x;
    int stride = gridDim.x * blockDim.x;
    const float STEP = 6.28318530717958647692f / 128.0f;

    for (int i = t; i < HH*18; i += stride) {
        int h = i / 18, k = i % 18;
        if (k < 17) {
            int m = (k * h) & 127;
            float s, c; sincosf(STEP * (float)m, &s, &c);
            g_TA2[i] = pk(c, -s);
        } else g_TA2[i] = 0ull;
    }
    for (int i = t; i < WW*MY; i += stride) {
        int w = i / MY, ky = i % MY;
        int m = (ky * w) & 127;
        float s, c; sincosf(STEP * (float)m, &s, &c);
        g_TBc[i] = pk(c, c);
        g_TBs[i] = pk(s, s);
    }
    for (int i = t; i < 128; i += stride) {
        float s, c; sincosf(STEP * (float)i, &s, &c);
        g_TP[i].x = pk(c, c);
        g_TP[i].y = pk(s, s);
    }
    for (int i = t; i < WW*8; i += stride) {
        int w = i / 8, j = i % 8;
        int k0 = 2*j, k1 = 2*j + 1;
        float s0, c0, s1, c1;
        sincosf(STEP * (float)((k0 * w) & 127), &s0, &c0);
        sincosf(STEP * (float)((k1 * w) & 127), &s1, &c1);
        float f0 = ((k0 == 0) ? 1.f : 2.f) / 16384.f;
        float f1 = 2.f / 16384.f;
        g_TC2[i] = pk(f0 * c0, f1 * c1);
        g_TS2[i] = pk(-f0 * s0, -f1 * s1);
    }
}

// ---------------- stage A: partial DFT over h, h-pair symmetry, 2x unroll ----------------
__global__ __launch_bounds__(256) void k_stageA(const float* __restrict__ x) {
    __shared__ ulonglong2 sTA[64*9];              // rows h = 0..63
    int b = blockIdx.y, wt = blockIdx.x;
    const ulonglong2* gTA = (const ulonglong2*)g_TA2;
    for (int i = threadIdx.x; i < 64*9; i += 256) sTA[i] = gTA[i];
    __syncthreads();

    int tid = threadIdx.x;
    int c = tid & 63;
    int w = wt*4 + (tid >> 6);
    const float* xb = x + (size_t)b * HH * WW * CC + (size_t)w * CC + c;

    u64 a[18];
    {   // h = 0 and h = 64 singles
        float x0  = xb[0];
        float x64 = xb[(size_t)64*WW*CC];
        float ep = x0 + x64, em = x0 - x64;
#pragma unroll
        for (int k = 0; k < 17; k++) a[k] = pk((k & 1) ? em : ep, 0.f);
        a[17] = 0ull;
    }

    float va0 = xb[(size_t)1*WW*CC];
    float vb0 = xb[(size_t)127*WW*CC];
    float va1 = xb[(size_t)2*WW*CC];
    float vb1 = xb[(size_t)126*WW*CC];

    for (int p = 1; p <= 61; p += 2) {
        float na0 = xb[(size_t)(p+2)*WW*CC];
        float nb0 = xb[(size_t)(126-p)*WW*CC];
        float na1 = 0.f, nb1 = 0.f;
        if (p < 61) {
            na1 = xb[(size_t)(p+3)*WW*CC];
            nb1 = xb[(size_t)(125-p)*WW*CC];
        }
        u64 sd0 = pk(va0 + vb0, va0 - vb0);
        u64 sd1 = pk(va1 + vb1, va1 - vb1);
#pragma unroll
        for (int q = 0; q < 9; q++) {
            ulonglong2 tw = sTA[p*9 + q];
            fma2(a[2*q],   sd0, tw.x);
            fma2(a[2*q+1], sd0, tw.y);
        }
#pragma unroll
        for (int q = 0; q < 9; q++) {
            ulonglong2 tw = sTA[(p+1)*9 + q];
            fma2(a[2*q],   sd1, tw.x);
            fma2(a[2*q+1], sd1, tw.y);
        }
        va0 = na0; vb0 = nb0; va1 = na1; vb1 = nb1;
    }
    {   // tail p = 63
        u64 sd = pk(va0 + vb0, va0 - vb0);
#pragma unroll
        for (int q = 0; q < 9; q++) {
            ulonglong2 tw = sTA[63*9 + q];
            fma2(a[2*q],   sd, tw.x);
            fma2(a[2*q+1], sd, tw.y);
        }
    }
#pragma unroll
    for (int k = 0; k < 17; k++)
        g_X1[((size_t)(b*NK + k)*WW + w)*CC + c] = a[k];
}

// ---------------- stage B: partial DFT over w, w-pair symmetry, 2x unroll ----------------
__global__ __launch_bounds__(256) void k_stageB() {
    __shared__ __align__(16) u64 sCC[64*MY];
    __shared__ __align__(16) u64 sSS[64*MY];
    int b = blockIdx.y, k = blockIdx.x;   // 0..16
    for (int i = threadIdx.x; i < 64*MY; i += 256) { sCC[i] = g_TBc[i]; sSS[i] = g_TBs[i]; }
    __syncthreads();

    int tid = threadIdx.x;
    int c  = tid & 63;
    int kg = tid >> 6;
    const u64* xp = g_X1 + (size_t)(b*NK + k)*WW*CC;

    u64 P[4], Q[4] = {0,0,0,0};
    {
        float2 f0  = upk(xp[c]);
        float2 f64 = upk(xp[64*CC + c]);
#pragma unroll
        for (int j = 0; j < 4; j++) {
            int ky = kg*4 + j;
            float sx = (ky & 1) ? -f64.x : f64.x;
            float sy = (ky & 1) ? -f64.y : f64.y;
            P[j] = pk(f0.x + sx, f0.y + sy);
        }
    }

    float2 fa0 = upk(xp[1*CC + c]);
    float2 fb0 = upk(xp[127*CC + c]);
    float2 fa1 = upk(xp[2*CC + c]);
    float2 fb1 = upk(xp[126*CC + c]);

    for (int w = 1; w <= 61; w += 2) {
        float2 nfa0 = upk(xp[(w+2)*CC + c]);
        float2 nfb0 = upk(xp[(126-w)*CC + c]);
        float2 nfa1 = make_float2(0.f, 0.f), nfb1 = make_float2(0.f, 0.f);
        if (w < 61) {
            nfa1 = upk(xp[(w+3)*CC + c]);
            nfb1 = upk(xp[(125-w)*CC + c]);
        }
        u64 Vs0 = pk(fa0.x + fb0.x, fa0.y + fb0.y);
        u64 Vd0 = pk(fa0.y - fb0.y, fb0.x - fa0.x);
        u64 Vs1 = pk(fa1.x + fb1.x, fa1.y + fb1.y);
        u64 Vd1 = pk(fa1.y - fb1.y, fb1.x - fa1.x);
        {
            const ulonglong2* cp = (const ulonglong2*)&sCC[w*MY + kg*4];
            const ulonglong2* sp = (const ulonglong2*)&sSS[w*MY + kg*4];
            ulonglong2 c01 = cp[0], c23 = cp[1];
            ulonglong2 s01 = sp[0], s23 = sp[1];
            fma2(P[0], Vs0, c01.x);  fma2(Q[0], Vd0, s01.x);
            fma2(P[1], Vs0, c01.y);  fma2(Q[1], Vd0, s01.y);
            fma2(P[2], Vs0, c23.x);  fma2(Q[2], Vd0, s23.x);
            fma2(P[3], Vs0, c23.y);  fma2(Q[3], Vd0, s23.y);
        }
        {
            const ulonglong2* cp = (const ulonglong2*)&sCC[(w+1)*MY + kg*4];
            const ulonglong2* sp = (const ulonglong2*)&sSS[(w+1)*MY + kg*4];
            ulonglong2 c01 = cp[0], c23 = cp[1];
            ulonglong2 s01 = sp[0], s23 = sp[1];
            fma2(P[0], Vs1, c01.x);  fma2(Q[0], Vd1, s01.x);
            fma2(P[1], Vs1, c01.y);  fma2(Q[1], Vd1, s01.y);
            fma2(P[2], Vs1, c23.x);  fma2(Q[2], Vd1, s23.x);
            fma2(P[3], Vs1, c23.y);  fma2(Q[3], Vd1, s23.y);
        }
        fa0 = nfa0; fb0 = nfb0; fa1 = nfa1; fb1 = nfb1;
    }
    {   // tail w = 63 (mirror = 65)
        u64 Vs = pk(fa0.x + fb0.x, fa0.y + fb0.y);
        u64 Vd = pk(fa0.y - fb0.y, fb0.x - fa0.x);
        const ulonglong2* cp = (const ulonglong2*)&sCC[63*MY + kg*4];
        const ulonglong2* sp = (const ulonglong2*)&sSS[63*MY + kg*4];
        ulonglong2 c01 = cp[0], c23 = cp[1];
        ulonglong2 s01 = sp[0], s23 = sp[1];
        fma2(P[0], Vs, c01.x);  fma2(Q[0], Vd, s01.x);
        fma2(P[1], Vs, c01.y);  fma2(Q[1], Vd, s01.y);
        fma2(P[2], Vs, c23.x);  fma2(Q[2], Vd, s23.x);
        fma2(P[3], Vs, c23.y);  fma2(Q[3], Vd, s23.y);
    }
    if (k < 16) {
#pragma unroll
        for (int j = 0; j < 4; j++) {
            int ky = kg*4 + j;
            float2 p = upk(P[j]), q = upk(Q[j]);
            g_Y[((size_t)(b*32 + k)*MY + ky)*CC + c] = pk(p.x + q.x, p.y + q.y);
        }
    }
    if (k >= 1) {
        int r2 = 32 - k;
#pragma unroll
        for (int j = 0; j < 4; j++) {
            int ky = kg*4 + j;
            float2 p = upk(P[j]), q = upk(Q[j]);
            g_Y[((size_t)(b*32 + r2)*MY + ky)*CC + c] = pk(p.x - q.x, q.y - p.y);
        }
    }
}

// ---------------- stage C: complex mode mixing, cp.async W staging, batch-split 2x ----------------
__global__ __launch_bounds__(256) void k_stageC(const float* __restrict__ w1r,
                                                const float* __restrict__ w1i,
                                                const float* __restrict__ w2r,
                                                const float* __restrict__ w2i) {
    extern __shared__ __align__(16) float smem[];
    float* sWr  = smem;
    float* sWi  = smem + 4096;
    float* sYre = smem + 8192;
    float* sYim = sYre + 64*20;

    int ky = blockIdx.x, r = blockIdx.y;
    int bh = blockIdx.z;                 // batch half: 0 or 1
    int tid = threadIdx.x;

    const float* __restrict__ Wr;
    const float* __restrict__ Wi;
    if (r < 16) {
        Wr = w1r + (size_t)((r*16 + ky)*64)*64;
        Wi = w1i + (size_t)((r*16 + ky)*64)*64;
    } else {
        Wr = w2r + (size_t)(((r-16)*16 + ky)*64)*64;
        Wi = w2i + (size_t)(((r-16)*16 + ky)*64)*64;
    }

    {
        unsigned swr = sptr(sWr), swi = sptr(sWi);
#pragma unroll
        for (int j = 0; j < 4; j++) {
            int i = tid + j*256;
            CP16(swr + i*16, Wr + i*4);
            CP16(swi + i*16, Wi + i*4);
        }
        asm volatile("cp.async.commit_group;");
    }

    // Y transpose: 16 batches x 64 channels
    for (int idx = tid; idx < 1024; idx += 256) {
        int bb = idx >> 6, cc2 = idx & 63;
        float2 f = upk(g_Y[((size_t)((bh*16 + bb)*32 + r)*MY + ky)*CC + cc2]);
        sYre[cc2*20 + bb] = f.x;
        sYim[cc2*20 + bb] = f.y;
    }
    asm volatile("cp.async.wait_group 0;");
    __syncthreads();

    int o  = tid & 63;
    int bg = tid >> 6;                   // 4 groups, each 4 batches (2 pairs)
    u64 P1[2] = {0,0}, P2[2] = {0,0}, P3[2] = {0,0}, P4[2] = {0,0};

    for (int i = 0; i < 64; i++) {
        float wr = sWr[i*64 + o];
        float wi = sWi[i*64 + o];
        u64 wrp = pk(wr, wr);
        u64 wip = pk(wi, wi);
        ulonglong2 yr = *(const ulonglong2*)&sYre[i*20 + bg*4];
        ulonglong2 yi = *(const ulonglong2*)&sYim[i*20 + bg*4];
        fma2(P1[0], yr.x, wrp);  fma2(P2[0], yi.x, wip);
        fma2(P3[0], yr.x, wip);  fma2(P4[0], yi.x, wrp);
        fma2(P1[1], yr.y, wrp);  fma2(P2[1], yi.y, wip);
        fma2(P3[1], yr.y, wip);  fma2(P4[1], yi.y, wrp);
    }
#pragma unroll
    for (int bp = 0; bp < 2; bp++) {
        int bb = bh*16 + bg*4 + bp*2;
        float2 p1 = upk(P1[bp]), p2 = upk(P2[bp]);
        float2 p3 = upk(P3[bp]), p4 = upk(P4[bp]);
        g_G[((size_t)(bb    *MY + ky)*32 + r)*CC + o] = pk(p1.x - p2.x, p3.x + p4.x);
        g_G[((size_t)((bb+1)*MY + ky)*32 + r)*CC + o] = pk(p1.y - p2.y, p3.y + p4.y);
    }
}

// ---------------- stage D1: inverse DFT over h, r-pair + h-mirror symmetry ----------------
__global__ __launch_bounds__(512) void k_stageD1() {
    __shared__ __align__(16) u64 sG[32*64];
    __shared__ ulonglong2 sTP[128];
    int ky = blockIdx.x, b = blockIdx.y;
    int tid = threadIdx.x;
    for (int i = tid; i < 2048; i += 512)
        sG[i] = g_G[((size_t)(b*MY + ky)*32 + (i >> 6))*CC + (i & 63)];
    for (int i = tid; i < 128; i += 512) sTP[i] = g_TP[i];
    __syncthreads();

    int c  = tid & 63;
    int hg = tid >> 6;
    int hbase = 1 + hg*8;

    u64 mc[8], ms[8];
#pragma unroll
    for (int q = 0; q < 8; q++) { mc[q] = 0ull; ms[q] = 0ull; }
    u64 g0 = sG[c];
    u64 Ssum = 0ull;

#pragma unroll
    for (int r = 1; r <= 16; r++) {
        u64 S, Dp;
        if (r < 16) {
            float2 ga = upk(sG[r*64 + c]);
            float2 gb = upk(sG[(32 - r)*64 + c]);
            S  = pk(ga.x + gb.x, ga.y + gb.y);
            Dp = pk(gb.y - ga.y, ga.x - gb.x);
        } else {
            float2 g = upk(sG[16*64 + c]);
            S  = pk(g.x, g.y);
            Dp = pk(g.y, -g.x);
        }
        if (hg == 0) add2(Ssum, S);
        int mm = (r * hbase) & 127;
#pragma unroll
        for (int hh = 0; hh < 8; hh++) {
            ulonglong2 t = sTP[mm];
            fma2(mc[hh], S,  t.x);
            fma2(ms[hh], Dp, t.y);
            mm = (mm + r) & 127;
        }
    }

    float2 fg0 = upk(g0);
    size_t base = (size_t)(b*MY + ky)*HH;
#pragma unroll
    for (int hh = 0; hh < 8; hh++) {
        int h = hbase + hh;
        float2 c2 = upk(mc[hh]), s2 = upk(ms[hh]);
        float tre = fg0.x + c2.x, tim = fg0.y + c2.y;
        size_t off = (base + h)*CC + c;
        g_Mre[off] = tre + s2.x;
        g_Mim[off] = tim + s2.y;
        if (h < 64) {
            size_t off2 = (base + 128 - h)*CC + c;
            g_Mre[off2] = tre - s2.x;
            g_Mim[off2] = tim - s2.y;
        }
    }
    if (hg == 0) {
        float2 fs = upk(Ssum);
        size_t off = base*CC + c;
        g_Mre[off] = fg0.x + fs.x;
        g_Mim[off] = fg0.y + fs.y;
    }
}

// ---------------- stage E: 2 rows per block, double-buffered cp.async ----------------
// dynamic smem: xsA[4096] u64 | xsB[4096] u64 | sTC[1024] u64 | sTS[1024] u64 = 81920 bytes
__global__ __launch_bounds__(256, 2) void k_stageE(const float* __restrict__ x,
                                                   const float* __restrict__ Kd,
                                                   const float* __restrict__ bias,
                                                   float* __restrict__ out) {
    extern __shared__ __align__(16) u64 dsm[];
    u64* xsA = dsm;              // 4096 u64 = row h0
    u64* xsB = dsm + 4096;       // 4096 u64 = row h1
    u64* sTC = dsm + 8192;       // 1024 u64
    u64* sTS = sTC + 1024;       // 1024 u64

    int h0 = blockIdx.x * 2, b = blockIdx.y;
    int tid = threadIdx.x;
    int c  = tid & 63;
    int wg = tid >> 6;

    const float* xrow0 = x + ((size_t)(b*HH + h0)*WW)*CC;
    const float* xrow1 = xrow0 + (size_t)WW*CC;
    float* orow0 = out + ((size_t)(b*HH + h0)*WW)*CC;
    float* orow1 = orow0 + (size_t)WW*CC;

    // group 0: row h0 + twiddle tables
    {
        unsigned sx = sptr(xsA);
#pragma unroll
        for (int j = 0; j < 8; j++) {
            int i = tid + j*256;
            CP16(sx + i*16, xrow0 + i*4);
        }
        unsigned stc = sptr(sTC), sts = sptr(sTS);
#pragma unroll
        for (int j = 0; j < 2; j++) {
            int i = tid + j*256;
            CP16(stc + i*16, (const float*)g_TC2 + i*4);
            CP16(sts + i*16, (const float*)g_TS2 + i*4);
        }
        asm volatile("cp.async.commit_group;");
    }
    // group 1: row h1
    {
        unsigned sx = sptr(xsB);
#pragma unroll
        for (int j = 0; j < 8; j++) {
            int i = tid + j*256;
            CP16(sx + i*16, xrow1 + i*4);
        }
        asm volatile("cp.async.commit_group;");
    }

    // overlapped register prefetch: Kp, R2/I2 row0, bias
    u64 Kp[32];
#pragma unroll
    for (int i = 0; i < 32; i++)
        Kp[i] = pk(Kd[(2*i)*64 + c], Kd[(2*i+1)*64 + c]);

    u64 R2[8], I2[8];
#pragma unroll
    for (int j = 0; j < 8; j++) {
        size_t o0 = ((size_t)(b*MY + 2*j    )*HH + h0)*CC + c;
        size_t o1 = ((size_t)(b*MY + 2*j + 1)*HH + h0)*CC + c;
        R2[j] = pk(g_Mre[o0], g_Mre[o1]);
        I2[j] = pk(g_Mim[o0], g_Mim[o1]);
    }
    float bc = bias[c];

    asm volatile("cp.async.wait_group 1;");   // row0 + tables ready
    __syncthreads();

    // ---- row h0 ----
    for (int ww = 0; ww < 32; ww++) {
        int w = wg*32 + ww;
        u64 acc0 = pk(bc, 0.f);
        u64 acc1 = 0ull;
        const ulonglong2* xv = (const ulonglong2*)&xsA[w*32];
#pragma unroll
        for (int t = 0; t < 16; t++) {
            ulonglong2 q = xv[t];
            fma2(acc0, q.x, Kp[2*t]);
            fma2(acc1, q.y, Kp[2*t + 1]);
        }
        const ulonglong2* tcp = (const ulonglong2*)&sTC[w*8];
        const ulonglong2* tsp = (const ulonglong2*)&sTS[w*8];
#pragma unroll
        for (int t = 0; t < 4; t++) {
            ulonglong2 tc = tcp[t];
            ulonglong2 ts = tsp[t];
            fma2(acc0, R2[2*t],     tc.x);
            fma2(acc1, R2[2*t + 1], tc.y);
            fma2(acc0, I2[2*t],     ts.x);
            fma2(acc1, I2[2*t + 1], ts.y);
        }
        float2 s0 = upk(acc0), s1 = upk(acc1);
        float xval = ((const float*)xsA)[w*64 + c];
        float u = xval + s0.x + s0.y + s1.x + s1.y;
        float u3 = u*u*u;
        float t = fast_tanh(0.7978845608028654f*(u + 0.044715f*u3));
        orow0[(size_t)w*64 + c] = 0.5f*u*(1.f + t);
    }

    // prefetch R2/I2 for row h1
#pragma unroll
    for (int j = 0; j < 8; j++) {
        size_t o0 = ((size_t)(b*MY + 2*j    )*HH + h0 + 1)*CC + c;
        size_t o1 = ((size_t)(b*MY + 2*j + 1)*HH + h0 + 1)*CC + c;
        R2[j] = pk(g_Mre[o0], g_Mre[o1]);
        I2[j] = pk(g_Mim[o0], g_Mim[o1]);
    }

    asm volatile("cp.async.wait_group 0;");   // row1 ready
    __syncthreads();

    // ---- row h1 ----
    for (int ww = 0; ww < 32; ww++) {
        int w = wg*32 + ww;
        u64 acc0 = pk(bc, 0.f);
        u64 acc1 = 0ull;
        const ulonglong2* xv = (const ulonglong2*)&xsB[w*32];
#pragma unroll
        for (int t = 0; t < 16; t++) {
            ulonglong2 q = xv[t];
            fma2(acc0, q.x, Kp[2*t]);
            fma2(acc1, q.y, Kp[2*t + 1]);
        }
        const ulonglong2* tcp = (const ulonglong2*)&sTC[w*8];
        const ulonglong2* tsp = (const ulonglong2*)&sTS[w*8];
#pragma unroll
        for (int t = 0; t < 4; t++) {
            ulonglong2 tc = tcp[t];
            ulonglong2 ts = tsp[t];
            fma2(acc0, R2[2*t],     tc.x);
            fma2(acc1, R2[2*t + 1], tc.y);
            fma2(acc0, I2[2*t],     ts.x);
            fma2(acc1, I2[2*t + 1], ts.y);
        }
        float2 s0 = upk(acc0), s1 = upk(acc1);
        float xval = ((const float*)xsB)[w*64 + c];
        float u = xval + s0.x + s0.y + s1.x + s1.y;
        float u3 = u*u*u;
        float t = fast_tanh(0.7978845608028654f*(u + 0.044715f*u3));
        orow1[(size_t)w*64 + c] = 0.5f*u*(1.f + t);
    }
}

// ---------------- launch ----------------
extern "C" void kernel_launch(void* const* d_in, const int* in_sizes, int n_in,
                              void* d_out, int out_size) {
    const float* x    = (const float*)d_in[0];
    const float* w1r  = (const float*)d_in[1];
    const float* w1i  = (const float*)d_in[2];
    const float* w2r  = (const float*)d_in[3];
    const float* w2i  = (const float*)d_in[4];
    const float* Kd   = (const float*)d_in[5];
    const float* bias = (const float*)d_in[6];
    float* out = (float*)d_out;

    const int C_SMEM = (4096 + 4096 + 64*20 + 64*20) * 4;   // 43008 bytes
    const int E_SMEM = (4096 + 4096 + 1024 + 1024) * 8;     // 81920 bytes
    static int attr_set = 0;
    if (!attr_set) {
        cudaFuncSetAttribute(k_stageC, cudaFuncAttributeMaxDynamicSharedMemorySize, C_SMEM);
        cudaFuncSetAttribute(k_stageE, cudaFuncAttributeMaxDynamicSharedMemorySize, E_SMEM);
        attr_set = 1;
    }

    k_init<<<64, 256>>>();
    k_stageA<<<dim3(32, 32), 256>>>(x);
    k_stageB<<<dim3(17, 32), 256>>>();
    k_stageC<<<dim3(16, 32, 2), 256, C_SMEM>>>(w1r, w1i, w2r, w2i);
    k_stageD1<<<dim3(16, 32), 512>>>();
    k_stageE<<<dim3(64, 32), 256, E_SMEM>>>(x, Kd, bias, out);
}

// round 13
// speedup vs baseline: 1.0854x; 1.0854x over previous
#include <cuda_runtime.h>
#include <math.h>

#define BB 32
#define HH 128
#define WW 128
#define CC 64
#define MX 16
#define MY 16
#define NK 17

typedef unsigned long long u64;

__device__ __forceinline__ u64 pk(float a, float b) {
    u64 r; asm("mov.b64 %0, {%1,%2};" : "=l"(r) : "f"(a), "f"(b)); return r;
}
__device__ __forceinline__ float2 upk(u64 v) {
    float2 f; asm("mov.b64 {%0,%1}, %2;" : "=f"(f.x), "=f"(f.y) : "l"(v)); return f;
}
__device__ __forceinline__ void fma2(u64 &d, u64 a, u64 b) {
    asm("fma.rn.f32x2 %0, %1, %2, %0;" : "+l"(d) : "l"(a), "l"(b));
}
__device__ __forceinline__ void add2(u64 &d, u64 a) {
    asm("add.rn.f32x2 %0, %0, %1;" : "+l"(d) : "l"(a));
}
__device__ __forceinline__ float fast_tanh(float x) {
    float t; asm("tanh.approx.f32 %0, %1;" : "=f"(t) : "f"(x)); return t;
}
__device__ __forceinline__ unsigned sptr(const void* p) {
    unsigned a;
    asm("{ .reg .u64 t; cvta.to.shared.u64 t, %1; cvt.u32.u64 %0, t; }" : "=r"(a) : "l"(p));
    return a;
}
#define CP16(s, g) asm volatile("cp.async.cg.shared.global [%0], [%1], 16;" :: "r"(s), "l"(g))

// ---------------- scratch ----------------
__device__ __align__(16) u64 g_X1[BB*NK*WW*CC];        // (re,im)
__device__ __align__(16) u64 g_Y [BB*32*MY*CC];        // (re,im)
__device__ __align__(16) u64 g_G [BB*MY*32*CC];        // (re,im) [b][ky][r][c]
__device__ __align__(16) float g_Mre[BB*MY*HH*CC];
__device__ __align__(16) float g_Mim[BB*MY*HH*CC];

// twiddle tables
__device__ __align__(16) u64 g_TA2[HH*18];             // [h][k] pk(cos,-sin), k=17 pad 0
__device__ __align__(16) u64 g_TBc[WW*MY];             // pk(c,c)
__device__ __align__(16) u64 g_TBs[WW*MY];             // pk(s,s)
__device__ __align__(16) ulonglong2 g_TP[128];         // {pk(c,c), pk(s,s)}
__device__ __align__(16) u64 g_TC2[WW*8];
__device__ __align__(16) u64 g_TS2[WW*8];

// ---------------- init ----------------
__global__ void k_init() {
    int t = blockIdx.x * blockDim.x + threadIdx.x;
    int stride = gridDim.x * blockDim.x;
    const float STEP = 6.28318530717958647692f / 128.0f;

    for (int i = t; i < HH*18; i += stride) {
        int h = i / 18, k = i % 18;
        if (k < 17) {
            int m = (k * h) & 127;
            float s, c; sincosf(STEP * (float)m, &s, &c);
            g_TA2[i] = pk(c, -s);
        } else g_TA2[i] = 0ull;
    }
    for (int i = t; i < WW*MY; i += stride) {
        int w = i / MY, ky = i % MY;
        int m = (ky * w) & 127;
        float s, c; sincosf(STEP * (float)m, &s, &c);
        g_TBc[i] = pk(c, c);
        g_TBs[i] = pk(s, s);
    }
    for (int i = t; i < 128; i += stride) {
        float s, c; sincosf(STEP * (float)i, &s, &c);
        g_TP[i].x = pk(c, c);
        g_TP[i].y = pk(s, s);
    }
    for (int i = t; i < WW*8; i += stride) {
        int w = i / 8, j = i % 8;
        int k0 = 2*j, k1 = 2*j + 1;
        float s0, c0, s1, c1;
        sincosf(STEP * (float)((k0 * w) & 127), &s0, &c0);
        sincosf(STEP * (float)((k1 * w) & 127), &s1, &c1);
        float f0 = ((k0 == 0) ? 1.f : 2.f) / 16384.f;
        float f1 = 2.f / 16384.f;
        g_TC2[i] = pk(f0 * c0, f1 * c1);
        g_TS2[i] = pk(-f0 * s0, -f1 * s1);
    }
}

// ---------------- stage A: partial DFT over h, h-pair symmetry, 2x unroll ----------------
__global__ __launch_bounds__(256) void k_stageA(const float* __restrict__ x) {
    __shared__ ulonglong2 sTA[64*9];              // rows h = 0..63
    int b = blockIdx.y, wt = blockIdx.x;
    const ulonglong2* gTA = (const ulonglong2*)g_TA2;
    for (int i = threadIdx.x; i < 64*9; i += 256) sTA[i] = gTA[i];
    __syncthreads();

    int tid = threadIdx.x;
    int c = tid & 63;
    int w = wt*4 + (tid >> 6);
    const float* xb = x + (size_t)b * HH * WW * CC + (size_t)w * CC + c;

    u64 a[18];
    {   // h = 0 and h = 64 singles
        float x0  = xb[0];
        float x64 = xb[(size_t)64*WW*CC];
        float ep = x0 + x64, em = x0 - x64;
#pragma unroll
        for (int k = 0; k < 17; k++) a[k] = pk((k & 1) ? em : ep, 0.f);
        a[17] = 0ull;
    }

    float va0 = xb[(size_t)1*WW*CC];
    float vb0 = xb[(size_t)127*WW*CC];
    float va1 = xb[(size_t)2*WW*CC];
    float vb1 = xb[(size_t)126*WW*CC];

    for (int p = 1; p <= 61; p += 2) {
        float na0 = xb[(size_t)(p+2)*WW*CC];
        float nb0 = xb[(size_t)(126-p)*WW*CC];
        float na1 = 0.f, nb1 = 0.f;
        if (p < 61) {
            na1 = xb[(size_t)(p+3)*WW*CC];
            nb1 = xb[(size_t)(125-p)*WW*CC];
        }
        u64 sd0 = pk(va0 + vb0, va0 - vb0);
        u64 sd1 = pk(va1 + vb1, va1 - vb1);
#pragma unroll
        for (int q = 0; q < 9; q++) {
            ulonglong2 tw = sTA[p*9 + q];
            fma2(a[2*q],   sd0, tw.x);
            fma2(a[2*q+1], sd0, tw.y);
        }
#pragma unroll
        for (int q = 0; q < 9; q++) {
            ulonglong2 tw = sTA[(p+1)*9 + q];
            fma2(a[2*q],   sd1, tw.x);
            fma2(a[2*q+1], sd1, tw.y);
        }
        va0 = na0; vb0 = nb0; va1 = na1; vb1 = nb1;
    }
    {   // tail p = 63
        u64 sd = pk(va0 + vb0, va0 - vb0);
#pragma unroll
        for (int q = 0; q < 9; q++) {
            ulonglong2 tw = sTA[63*9 + q];
            fma2(a[2*q],   sd, tw.x);
            fma2(a[2*q+1], sd, tw.y);
        }
    }
#pragma unroll
    for (int k = 0; k < 17; k++)
        g_X1[((size_t)(b*NK + k)*WW + w)*CC + c] = a[k];
}

// ---------------- stage B: partial DFT over w, w-pair symmetry, 2x unroll ----------------
__global__ __launch_bounds__(256) void k_stageB() {
    __shared__ __align__(16) u64 sCC[64*MY];
    __shared__ __align__(16) u64 sSS[64*MY];
    int b = blockIdx.y, k = blockIdx.x;   // 0..16
    for (int i = threadIdx.x; i < 64*MY; i += 256) { sCC[i] = g_TBc[i]; sSS[i] = g_TBs[i]; }
    __syncthreads();

    int tid = threadIdx.x;
    int c  = tid & 63;
    int kg = tid >> 6;
    const u64* xp = g_X1 + (size_t)(b*NK + k)*WW*CC;

    u64 P[4], Q[4] = {0,0,0,0};
    {
        float2 f0  = upk(xp[c]);
        float2 f64 = upk(xp[64*CC + c]);
#pragma unroll
        for (int j = 0; j < 4; j++) {
            int ky = kg*4 + j;
            float sx = (ky & 1) ? -f64.x : f64.x;
            float sy = (ky & 1) ? -f64.y : f64.y;
            P[j] = pk(f0.x + sx, f0.y + sy);
        }
    }

    float2 fa0 = upk(xp[1*CC + c]);
    float2 fb0 = upk(xp[127*CC + c]);
    float2 fa1 = upk(xp[2*CC + c]);
    float2 fb1 = upk(xp[126*CC + c]);

    for (int w = 1; w <= 61; w += 2) {
        float2 nfa0 = upk(xp[(w+2)*CC + c]);
        float2 nfb0 = upk(xp[(126-w)*CC + c]);
        float2 nfa1 = make_float2(0.f, 0.f), nfb1 = make_float2(0.f, 0.f);
        if (w < 61) {
            nfa1 = upk(xp[(w+3)*CC + c]);
            nfb1 = upk(xp[(125-w)*CC + c]);
        }
        u64 Vs0 = pk(fa0.x + fb0.x, fa0.y + fb0.y);
        u64 Vd0 = pk(fa0.y - fb0.y, fb0.x - fa0.x);
        u64 Vs1 = pk(fa1.x + fb1.x, fa1.y + fb1.y);
        u64 Vd1 = pk(fa1.y - fb1.y, fb1.x - fa1.x);
        {
            const ulonglong2* cp = (const ulonglong2*)&sCC[w*MY + kg*4];
            const ulonglong2* sp = (const ulonglong2*)&sSS[w*MY + kg*4];
            ulonglong2 c01 = cp[0], c23 = cp[1];
            ulonglong2 s01 = sp[0], s23 = sp[1];
            fma2(P[0], Vs0, c01.x);  fma2(Q[0], Vd0, s01.x);
            fma2(P[1], Vs0, c01.y);  fma2(Q[1], Vd0, s01.y);
            fma2(P[2], Vs0, c23.x);  fma2(Q[2], Vd0, s23.x);
            fma2(P[3], Vs0, c23.y);  fma2(Q[3], Vd0, s23.y);
        }
        {
            const ulonglong2* cp = (const ulonglong2*)&sCC[(w+1)*MY + kg*4];
            const ulonglong2* sp = (const ulonglong2*)&sSS[(w+1)*MY + kg*4];
            ulonglong2 c01 = cp[0], c23 = cp[1];
            ulonglong2 s01 = sp[0], s23 = sp[1];
            fma2(P[0], Vs1, c01.x);  fma2(Q[0], Vd1, s01.x);
            fma2(P[1], Vs1, c01.y);  fma2(Q[1], Vd1, s01.y);
            fma2(P[2], Vs1, c23.x);  fma2(Q[2], Vd1, s23.x);
            fma2(P[3], Vs1, c23.y);  fma2(Q[3], Vd1, s23.y);
        }
        fa0 = nfa0; fb0 = nfb0; fa1 = nfa1; fb1 = nfb1;
    }
    {   // tail w = 63
        u64 Vs = pk(fa0.x + fb0.x, fa0.y + fb0.y);
        u64 Vd = pk(fa0.y - fb0.y, fb0.x - fa0.x);
        const ulonglong2* cp = (const ulonglong2*)&sCC[63*MY + kg*4];
        const ulonglong2* sp = (const ulonglong2*)&sSS[63*MY + kg*4];
        ulonglong2 c01 = cp[0], c23 = cp[1];
        ulonglong2 s01 = sp[0], s23 = sp[1];
        fma2(P[0], Vs, c01.x);  fma2(Q[0], Vd, s01.x);
        fma2(P[1], Vs, c01.y);  fma2(Q[1], Vd, s01.y);
        fma2(P[2], Vs, c23.x);  fma2(Q[2], Vd, s23.x);
        fma2(P[3], Vs, c23.y);  fma2(Q[3], Vd, s23.y);
    }
    if (k < 16) {
#pragma unroll
        for (int j = 0; j < 4; j++) {
            int ky = kg*4 + j;
            float2 p = upk(P[j]), q = upk(Q[j]);
            g_Y[((size_t)(b*32 + k)*MY + ky)*CC + c] = pk(p.x + q.x, p.y + q.y);
        }
    }
    if (k >= 1) {
        int r2 = 32 - k;
#pragma unroll
        for (int j = 0; j < 4; j++) {
            int ky = kg*4 + j;
            float2 p = upk(P[j]), q = upk(Q[j]);
            g_Y[((size_t)(b*32 + r2)*MY + ky)*CC + c] = pk(p.x - q.x, q.y - p.y);
        }
    }
}

// ---------------- stage C: complex mode mixing, cp.async W staging, batch-split 2x ----------------
__global__ __launch_bounds__(256) void k_stageC(const float* __restrict__ w1r,
                                                const float* __restrict__ w1i,
                                                const float* __restrict__ w2r,
                                                const float* __restrict__ w2i) {
    extern __shared__ __align__(16) float smem[];
    float* sWr  = smem;
    float* sWi  = smem + 4096;
    float* sYre = smem + 8192;
    float* sYim = sYre + 64*20;

    int ky = blockIdx.x, r = blockIdx.y;
    int bh = blockIdx.z;                 // batch half: 0 or 1
    int tid = threadIdx.x;

    const float* __restrict__ Wr;
    const float* __restrict__ Wi;
    if (r < 16) {
        Wr = w1r + (size_t)((r*16 + ky)*64)*64;
        Wi = w1i + (size_t)((r*16 + ky)*64)*64;
    } else {
        Wr = w2r + (size_t)(((r-16)*16 + ky)*64)*64;
        Wi = w2i + (size_t)(((r-16)*16 + ky)*64)*64;
    }

    {
        unsigned swr = sptr(sWr), swi = sptr(sWi);
#pragma unroll
        for (int j = 0; j < 4; j++) {
            int i = tid + j*256;
            CP16(swr + i*16, Wr + i*4);
            CP16(swi + i*16, Wi + i*4);
        }
        asm volatile("cp.async.commit_group;");
    }

    // Y transpose: 16 batches x 64 channels
    for (int idx = tid; idx < 1024; idx += 256) {
        int bb = idx >> 6, cc2 = idx & 63;
        float2 f = upk(g_Y[((size_t)((bh*16 + bb)*32 + r)*MY + ky)*CC + cc2]);
        sYre[cc2*20 + bb] = f.x;
        sYim[cc2*20 + bb] = f.y;
    }
    asm volatile("cp.async.wait_group 0;");
    __syncthreads();

    int o  = tid & 63;
    int bg = tid >> 6;                   // 4 groups, each 4 batches (2 pairs)
    u64 P1[2] = {0,0}, P2[2] = {0,0}, P3[2] = {0,0}, P4[2] = {0,0};

    for (int i = 0; i < 64; i++) {
        float wr = sWr[i*64 + o];
        float wi = sWi[i*64 + o];
        u64 wrp = pk(wr, wr);
        u64 wip = pk(wi, wi);
        ulonglong2 yr = *(const ulonglong2*)&sYre[i*20 + bg*4];
        ulonglong2 yi = *(const ulonglong2*)&sYim[i*20 + bg*4];
        fma2(P1[0], yr.x, wrp);  fma2(P2[0], yi.x, wip);
        fma2(P3[0], yr.x, wip);  fma2(P4[0], yi.x, wrp);
        fma2(P1[1], yr.y, wrp);  fma2(P2[1], yi.y, wip);
        fma2(P3[1], yr.y, wip);  fma2(P4[1], yi.y, wrp);
    }
#pragma unroll
    for (int bp = 0; bp < 2; bp++) {
        int bb = bh*16 + bg*4 + bp*2;
        float2 p1 = upk(P1[bp]), p2 = upk(P2[bp]);
        float2 p3 = upk(P3[bp]), p4 = upk(P4[bp]);
        g_G[((size_t)(bb    *MY + ky)*32 + r)*CC + o] = pk(p1.x - p2.x, p3.x + p4.x);
        g_G[((size_t)((bb+1)*MY + ky)*32 + r)*CC + o] = pk(p1.y - p2.y, p3.y + p4.y);
    }
}

// ---------------- stage D1: inverse DFT over h, r-pair + h-mirror symmetry ----------------
__global__ __launch_bounds__(512) void k_stageD1() {
    __shared__ __align__(16) u64 sG[32*64];
    __shared__ ulonglong2 sTP[128];
    int ky = blockIdx.x, b = blockIdx.y;
    int tid = threadIdx.x;
    for (int i = tid; i < 2048; i += 512)
        sG[i] = g_G[((size_t)(b*MY + ky)*32 + (i >> 6))*CC + (i & 63)];
    for (int i = tid; i < 128; i += 512) sTP[i] = g_TP[i];
    __syncthreads();

    int c  = tid & 63;
    int hg = tid >> 6;
    int hbase = 1 + hg*8;

    u64 mc[8], ms[8];
#pragma unroll
    for (int q = 0; q < 8; q++) { mc[q] = 0ull; ms[q] = 0ull; }
    u64 g0 = sG[c];
    u64 Ssum = 0ull;

#pragma unroll
    for (int r = 1; r <= 16; r++) {
        u64 S, Dp;
        if (r < 16) {
            float2 ga = upk(sG[r*64 + c]);
            float2 gb = upk(sG[(32 - r)*64 + c]);
            S  = pk(ga.x + gb.x, ga.y + gb.y);
            Dp = pk(gb.y - ga.y, ga.x - gb.x);
        } else {
            float2 g = upk(sG[16*64 + c]);
            S  = pk(g.x, g.y);
            Dp = pk(g.y, -g.x);
        }
        if (hg == 0) add2(Ssum, S);
        int mm = (r * hbase) & 127;
#pragma unroll
        for (int hh = 0; hh < 8; hh++) {
            ulonglong2 t = sTP[mm];
            fma2(mc[hh], S,  t.x);
            fma2(ms[hh], Dp, t.y);
            mm = (mm + r) & 127;
        }
    }

    float2 fg0 = upk(g0);
    size_t base = (size_t)(b*MY + ky)*HH;
#pragma unroll
    for (int hh = 0; hh < 8; hh++) {
        int h = hbase + hh;
        float2 c2 = upk(mc[hh]), s2 = upk(ms[hh]);
        float tre = fg0.x + c2.x, tim = fg0.y + c2.y;
        size_t off = (base + h)*CC + c;
        g_Mre[off] = tre + s2.x;
        g_Mim[off] = tim + s2.y;
        if (h < 64) {
            size_t off2 = (base + 128 - h)*CC + c;
            g_Mre[off2] = tre - s2.x;
            g_Mim[off2] = tim - s2.y;
        }
    }
    if (hg == 0) {
        float2 fs = upk(Ssum);
        size_t off = base*CC + c;
        g_Mre[off] = fg0.x + fs.x;
        g_Mim[off] = fg0.y + fs.y;
    }
}

// ---------------- stage E: full-row cp.async staging + 2-chain dense/spectral + GELU ----------------
// dynamic smem: xs2[4096] u64 | sTC[1024] u64 | sTS[1024] u64 = 49152 bytes
__global__ __launch_bounds__(256, 2) void k_stageE(const float* __restrict__ x,
                                                   const float* __restrict__ Kd,
                                                   const float* __restrict__ bias,
                                                   float* __restrict__ out) {
    extern __shared__ __align__(16) u64 dsm[];
    u64* xs2 = dsm;              // 4096 u64 = full 128-pixel row
    u64* sTC = dsm + 4096;       // 1024 u64
    u64* sTS = sTC + 1024;       // 1024 u64

    int h = blockIdx.x, b = blockIdx.y;
    int tid = threadIdx.x;
    int c  = tid & 63;
    int wg = tid >> 6;

    const float* xrow = x   + ((size_t)(b*HH + h)*WW)*CC;
    float*       orow = out + ((size_t)(b*HH + h)*WW)*CC;

    // fire-and-forget staging of x row + twiddle tables
    {
        unsigned sx = sptr(xs2);
#pragma unroll
        for (int j = 0; j < 8; j++) {
            int i = tid + j*256;
            CP16(sx + i*16, xrow + i*4);
        }
        unsigned stc = sptr(sTC), sts = sptr(sTS);
#pragma unroll
        for (int j = 0; j < 2; j++) {
            int i = tid + j*256;
            CP16(stc + i*16, (const float*)g_TC2 + i*4);
            CP16(sts + i*16, (const float*)g_TS2 + i*4);
        }
        asm volatile("cp.async.commit_group;");
    }

    // overlapped register prefetch: Kp, R2/I2, bias
    u64 Kp[32];
#pragma unroll
    for (int i = 0; i < 32; i++)
        Kp[i] = pk(Kd[(2*i)*64 + c], Kd[(2*i+1)*64 + c]);

    u64 R2[8], I2[8];
#pragma unroll
    for (int j = 0; j < 8; j++) {
        size_t o0 = ((size_t)(b*MY + 2*j    )*HH + h)*CC + c;
        size_t o1 = ((size_t)(b*MY + 2*j + 1)*HH + h)*CC + c;
        R2[j] = pk(g_Mre[o0], g_Mre[o1]);
        I2[j] = pk(g_Mim[o0], g_Mim[o1]);
    }
    float bc = bias[c];

    asm volatile("cp.async.wait_group 0;");
    __syncthreads();

    for (int ww = 0; ww < 32; ww++) {
        int w = wg*32 + ww;
        u64 acc0 = pk(bc, 0.f);
        u64 acc1 = 0ull;
        const ulonglong2* xv = (const ulonglong2*)&xs2[w*32];
#pragma unroll
        for (int t = 0; t < 16; t++) {
            ulonglong2 q = xv[t];
            fma2(acc0, q.x, Kp[2*t]);
            fma2(acc1, q.y, Kp[2*t + 1]);
        }
        const ulonglong2* tcp = (const ulonglong2*)&sTC[w*8];
        const ulonglong2* tsp = (const ulonglong2*)&sTS[w*8];
#pragma unroll
        for (int t = 0; t < 4; t++) {
            ulonglong2 tc = tcp[t];
            ulonglong2 ts = tsp[t];
            fma2(acc0, R2[2*t],     tc.x);
            fma2(acc1, R2[2*t + 1], tc.y);
            fma2(acc0, I2[2*t],     ts.x);
            fma2(acc1, I2[2*t + 1], ts.y);
        }
        float2 s0 = upk(acc0), s1 = upk(acc1);
        float xval = ((const float*)xs2)[w*64 + c];
        float u = xval + s0.x + s0.y + s1.x + s1.y;
        float u3 = u*u*u;
        float t = fast_tanh(0.7978845608028654f*(u + 0.044715f*u3));
        orow[(size_t)w*64 + c] = 0.5f*u*(1.f + t);
    }
}

// ---------------- launch ----------------
extern "C" void kernel_launch(void* const* d_in, const int* in_sizes, int n_in,
                              void* d_out, int out_size) {
    const float* x    = (const float*)d_in[0];
    const float* w1r  = (const float*)d_in[1];
    const float* w1i  = (const float*)d_in[2];
    const float* w2r  = (const float*)d_in[3];
    const float* w2i  = (const float*)d_in[4];
    const float* Kd   = (const float*)d_in[5];
    const float* bias = (const float*)d_in[6];
    float* out = (float*)d_out;

    const int C_SMEM = (4096 + 4096 + 64*20 + 64*20) * 4;   // 43008 bytes
    const int E_SMEM = (4096 + 1024 + 1024) * 8;            // 49152 bytes
    static int attr_set = 0;
    if (!attr_set) {
        cudaFuncSetAttribute(k_stageC, cudaFuncAttributeMaxDynamicSharedMemorySize, C_SMEM);
        cudaFuncSetAttribute(k_stageE, cudaFuncAttributeMaxDynamicSharedMemorySize, E_SMEM);
        attr_set = 1;
    }

    k_init<<<64, 256>>>();
    k_stageA<<<dim3(32, 32), 256>>>(x);
    k_stageB<<<dim3(17, 32), 256>>>();
    k_stageC<<<dim3(16, 32, 2), 256, C_SMEM>>>(w1r, w1i, w2r, w2i);
    k_stageD1<<<dim3(16, 32), 512>>>();
    k_stageE<<<dim3(128, 32), 256, E_SMEM>>>(x, Kd, bias, out);
}

// round 14
// speedup vs baseline: 1.1517x; 1.0611x over previous
#include <cuda_runtime.h>
#include <math.h>

#define BB 32
#define HH 128
#define WW 128
#define CC 64
#define MX 16
#define MY 16
#define NK 17

typedef unsigned long long u64;

__device__ __forceinline__ u64 pk(float a, float b) {
    u64 r; asm("mov.b64 %0, {%1,%2};" : "=l"(r) : "f"(a), "f"(b)); return r;
}
__device__ __forceinline__ float2 upk(u64 v) {
    float2 f; asm("mov.b64 {%0,%1}, %2;" : "=f"(f.x), "=f"(f.y) : "l"(v)); return f;
}
__device__ __forceinline__ void fma2(u64 &d, u64 a, u64 b) {
    asm("fma.rn.f32x2 %0, %1, %2, %0;" : "+l"(d) : "l"(a), "l"(b));
}
__device__ __forceinline__ void add2(u64 &d, u64 a) {
    asm("add.rn.f32x2 %0, %0, %1;" : "+l"(d) : "l"(a));
}
__device__ __forceinline__ float fast_tanh(float x) {
    float t; asm("tanh.approx.f32 %0, %1;" : "=f"(t) : "f"(x)); return t;
}
__device__ __forceinline__ unsigned sptr(const void* p) {
    unsigned a;
    asm("{ .reg .u64 t; cvta.to.shared.u64 t, %1; cvt.u32.u64 %0, t; }" : "=r"(a) : "l"(p));
    return a;
}
#define CP16(s, g) asm volatile("cp.async.cg.shared.global [%0], [%1], 16;" :: "r"(s), "l"(g))

// ---------------- scratch ----------------
__device__ __align__(16) u64 g_X1[BB*NK*WW*CC];        // (re,im)
__device__ __align__(16) u64 g_Y [BB*32*MY*CC];        // (re,im)
__device__ __align__(16) u64 g_G [BB*MY*32*CC];        // (re,im) [b][ky][r][c]
__device__ __align__(16) float g_Mre[BB*MY*HH*CC];
__device__ __align__(16) float g_Mim[BB*MY*HH*CC];

// twiddle tables
__device__ __align__(16) u64 g_TA2[HH*18];             // [h][k] pk(cos,-sin), k=17 pad 0
__device__ __align__(16) u64 g_TBc[WW*MY];             // pk(c,c)
__device__ __align__(16) u64 g_TBs[WW*MY];             // pk(s,s)
__device__ __align__(16) ulonglong2 g_TP[128];         // {pk(c,c), pk(s,s)}
__device__ __align__(16) u64 g_TC2[WW*8];
__device__ __align__(16) u64 g_TS2[WW*8];

// ---------------- init ----------------
__global__ void k_init() {
    int t = blockIdx.x * blockDim.x + threadIdx.x;
    int stride = gridDim.x * blockDim.x;
    const float STEP = 6.28318530717958647692f / 128.0f;

    for (int i = t; i < HH*18; i += stride) {
        int h = i / 18, k = i % 18;
        if (k < 17) {
            int m = (k * h) & 127;
            float s, c; sincosf(STEP * (float)m, &s, &c);
            g_TA2[i] = pk(c, -s);
        } else g_TA2[i] = 0ull;
    }
    for (int i = t; i < WW*MY; i += stride) {
        int w = i / MY, ky = i % MY;
        int m = (ky * w) & 127;
        float s, c; sincosf(STEP * (float)m, &s, &c);
        g_TBc[i] = pk(c, c);
        g_TBs[i] = pk(s, s);
    }
    for (int i = t; i < 128; i += stride) {
        float s, c; sincosf(STEP * (float)i, &s, &c);
        g_TP[i].x = pk(c, c);
        g_TP[i].y = pk(s, s);
    }
    for (int i = t; i < WW*8; i += stride) {
        int w = i / 8, j = i % 8;
        int k0 = 2*j, k1 = 2*j + 1;
        float s0, c0, s1, c1;
        sincosf(STEP * (float)((k0 * w) & 127), &s0, &c0);
        sincosf(STEP * (float)((k1 * w) & 127), &s1, &c1);
        float f0 = ((k0 == 0) ? 1.f : 2.f) / 16384.f;
        float f1 = 2.f / 16384.f;
        g_TC2[i] = pk(f0 * c0, f1 * c1);
        g_TS2[i] = pk(-f0 * s0, -f1 * s1);
    }
}

// ---------------- stage A: partial DFT over h, h-pair symmetry, cp.async chunked staging ----------------
// dynamic smem: sTA[576 ulonglong2 = 9216B] | buf[2][8192 floats] (low 16 rows + high 16 rows each)
__global__ __launch_bounds__(256, 2) void k_stageA(const float* __restrict__ x) {
    extern __shared__ __align__(16) u64 adsm[];
    ulonglong2* sTA = (ulonglong2*)adsm;          // 64*9 = 576 entries
    float* buf = (float*)(adsm + 1152);           // 2 * 8192 floats

    int b = blockIdx.y, wt = blockIdx.x;
    int tid = threadIdx.x;
    for (int i = tid; i < 576; i += 256) sTA[i] = ((const ulonglong2*)g_TA2)[i];

    const float* xb0 = x + (size_t)b * HH * WW * CC + (size_t)(wt*4) * CC;

    // issue chunk ci into buffer s: pairs p = 1+16ci .. 16+16ci
    // low rows h = p at buf[s][0..16KB), high rows h = 128-p at buf[s][16KB..32KB)
    auto issue = [&](int ci, int s) {
        unsigned sb = sptr(buf + s*8192);
        int p0 = 1 + 16*ci;
#pragma unroll
        for (int t = 0; t < 4; t++) {
            int idx = tid + t*256;            // 0..1023
            int j = idx >> 6, q = idx & 63;   // row j, 16B chunk q
            CP16(sb + j*1024 + q*16,         xb0 + (size_t)(p0 + j)*WW*CC + q*4);
            CP16(sb + 16384 + j*1024 + q*16, xb0 + (size_t)(128 - p0 - j)*WW*CC + q*4);
        }
        asm volatile("cp.async.commit_group;");
    };

    issue(0, 0);
    issue(1, 1);

    int c  = tid & 63;
    int wl = tid >> 6;
    int w  = wt*4 + wl;
    const float* xb = xb0 + (size_t)wl*CC + c;

    u64 a[18];
    {   // h = 0 and h = 64 singles (overlapped with cp.async)
        float x0  = xb[0];
        float x64 = xb[(size_t)64*WW*CC];
        float ep = x0 + x64, em = x0 - x64;
#pragma unroll
        for (int k = 0; k < 17; k++) a[k] = pk((k & 1) ? em : ep, 0.f);
        a[17] = 0ull;
    }

    for (int ci = 0; ci < 4; ci++) {
        if (ci < 3) asm volatile("cp.async.wait_group 1;");
        else        asm volatile("cp.async.wait_group 0;");
        __syncthreads();

        int s = ci & 1;
        const float* lo = buf + s*8192 + wl*64 + c;
        const float* hi = lo + 4096;
        int p0 = 1 + 16*ci;
        int npairs = (ci < 3) ? 16 : 15;      // chunk 3: p = 49..63
        for (int j = 0; j < npairs; j++) {
            float va = lo[j*256];
            float vb = hi[j*256];
            u64 sd = pk(va + vb, va - vb);
            const ulonglong2* tw = &sTA[(p0 + j)*9];
#pragma unroll
            for (int q = 0; q < 9; q++) {
                ulonglong2 t = tw[q];
                fma2(a[2*q],   sd, t.x);
                fma2(a[2*q+1], sd, t.y);
            }
        }
        __syncthreads();
        if (ci < 2) issue(ci + 2, s);
    }

#pragma unroll
    for (int k = 0; k < 17; k++)
        g_X1[((size_t)(b*NK + k)*WW + w)*CC + c] = a[k];
}

// ---------------- stage B: partial DFT over w, w-pair symmetry, 2x unroll ----------------
__global__ __launch_bounds__(256) void k_stageB() {
    __shared__ __align__(16) u64 sCC[64*MY];
    __shared__ __align__(16) u64 sSS[64*MY];
    int b = blockIdx.y, k = blockIdx.x;   // 0..16
    for (int i = threadIdx.x; i < 64*MY; i += 256) { sCC[i] = g_TBc[i]; sSS[i] = g_TBs[i]; }
    __syncthreads();

    int tid = threadIdx.x;
    int c  = tid & 63;
    int kg = tid >> 6;
    const u64* xp = g_X1 + (size_t)(b*NK + k)*WW*CC;

    u64 P[4], Q[4] = {0,0,0,0};
    {
        float2 f0  = upk(xp[c]);
        float2 f64 = upk(xp[64*CC + c]);
#pragma unroll
        for (int j = 0; j < 4; j++) {
            int ky = kg*4 + j;
            float sx = (ky & 1) ? -f64.x : f64.x;
            float sy = (ky & 1) ? -f64.y : f64.y;
            P[j] = pk(f0.x + sx, f0.y + sy);
        }
    }

    float2 fa0 = upk(xp[1*CC + c]);
    float2 fb0 = upk(xp[127*CC + c]);
    float2 fa1 = upk(xp[2*CC + c]);
    float2 fb1 = upk(xp[126*CC + c]);

    for (int w = 1; w <= 61; w += 2) {
        float2 nfa0 = upk(xp[(w+2)*CC + c]);
        float2 nfb0 = upk(xp[(126-w)*CC + c]);
        float2 nfa1 = make_float2(0.f, 0.f), nfb1 = make_float2(0.f, 0.f);
        if (w < 61) {
            nfa1 = upk(xp[(w+3)*CC + c]);
            nfb1 = upk(xp[(125-w)*CC + c]);
        }
        u64 Vs0 = pk(fa0.x + fb0.x, fa0.y + fb0.y);
        u64 Vd0 = pk(fa0.y - fb0.y, fb0.x - fa0.x);
        u64 Vs1 = pk(fa1.x + fb1.x, fa1.y + fb1.y);
        u64 Vd1 = pk(fa1.y - fb1.y, fb1.x - fa1.x);
        {
            const ulonglong2* cp = (const ulonglong2*)&sCC[w*MY + kg*4];
            const ulonglong2* sp = (const ulonglong2*)&sSS[w*MY + kg*4];
            ulonglong2 c01 = cp[0], c23 = cp[1];
            ulonglong2 s01 = sp[0], s23 = sp[1];
            fma2(P[0], Vs0, c01.x);  fma2(Q[0], Vd0, s01.x);
            fma2(P[1], Vs0, c01.y);  fma2(Q[1], Vd0, s01.y);
            fma2(P[2], Vs0, c23.x);  fma2(Q[2], Vd0, s23.x);
            fma2(P[3], Vs0, c23.y);  fma2(Q[3], Vd0, s23.y);
        }
        {
            const ulonglong2* cp = (const ulonglong2*)&sCC[(w+1)*MY + kg*4];
            const ulonglong2* sp = (const ulonglong2*)&sSS[(w+1)*MY + kg*4];
            ulonglong2 c01 = cp[0], c23 = cp[1];
            ulonglong2 s01 = sp[0], s23 = sp[1];
            fma2(P[0], Vs1, c01.x);  fma2(Q[0], Vd1, s01.x);
            fma2(P[1], Vs1, c01.y);  fma2(Q[1], Vd1, s01.y);
            fma2(P[2], Vs1, c23.x);  fma2(Q[2], Vd1, s23.x);
            fma2(P[3], Vs1, c23.y);  fma2(Q[3], Vd1, s23.y);
        }
        fa0 = nfa0; fb0 = nfb0; fa1 = nfa1; fb1 = nfb1;
    }
    {   // tail w = 63
        u64 Vs = pk(fa0.x + fb0.x, fa0.y + fb0.y);
        u64 Vd = pk(fa0.y - fb0.y, fb0.x - fa0.x);
        const ulonglong2* cp = (const ulonglong2*)&sCC[63*MY + kg*4];
        const ulonglong2* sp = (const ulonglong2*)&sSS[63*MY + kg*4];
        ulonglong2 c01 = cp[0], c23 = cp[1];
        ulonglong2 s01 = sp[0], s23 = sp[1];
        fma2(P[0], Vs, c01.x);  fma2(Q[0], Vd, s01.x);
        fma2(P[1], Vs, c01.y);  fma2(Q[1], Vd, s01.y);
        fma2(P[2], Vs, c23.x);  fma2(Q[2], Vd, s23.x);
        fma2(P[3], Vs, c23.y);  fma2(Q[3], Vd, s23.y);
    }
    if (k < 16) {
#pragma unroll
        for (int j = 0; j < 4; j++) {
            int ky = kg*4 + j;
            float2 p = upk(P[j]), q = upk(Q[j]);
            g_Y[((size_t)(b*32 + k)*MY + ky)*CC + c] = pk(p.x + q.x, p.y + q.y);
        }
    }
    if (k >= 1) {
        int r2 = 32 - k;
#pragma unroll
        for (int j = 0; j < 4; j++) {
            int ky = kg*4 + j;
            float2 p = upk(P[j]), q = upk(Q[j]);
            g_Y[((size_t)(b*32 + r2)*MY + ky)*CC + c] = pk(p.x - q.x, q.y - p.y);
        }
    }
}

// ---------------- stage C: complex mode mixing, cp.async W staging, batch-split 2x ----------------
__global__ __launch_bounds__(256) void k_stageC(const float* __restrict__ w1r,
                                                const float* __restrict__ w1i,
                                                const float* __restrict__ w2r,
                                                const float* __restrict__ w2i) {
    extern __shared__ __align__(16) float smem[];
    float* sWr  = smem;
    float* sWi  = smem + 4096;
    float* sYre = smem + 8192;
    float* sYim = sYre + 64*20;

    int ky = blockIdx.x, r = blockIdx.y;
    int bh = blockIdx.z;                 // batch half: 0 or 1
    int tid = threadIdx.x;

    const float* __restrict__ Wr;
    const float* __restrict__ Wi;
    if (r < 16) {
        Wr = w1r + (size_t)((r*16 + ky)*64)*64;
        Wi = w1i + (size_t)((r*16 + ky)*64)*64;
    } else {
        Wr = w2r + (size_t)(((r-16)*16 + ky)*64)*64;
        Wi = w2i + (size_t)(((r-16)*16 + ky)*64)*64;
    }

    {
        unsigned swr = sptr(sWr), swi = sptr(sWi);
#pragma unroll
        for (int j = 0; j < 4; j++) {
            int i = tid + j*256;
            CP16(swr + i*16, Wr + i*4);
            CP16(swi + i*16, Wi + i*4);
        }
        asm volatile("cp.async.commit_group;");
    }

    // Y transpose: 16 batches x 64 channels
    for (int idx = tid; idx < 1024; idx += 256) {
        int bb = idx >> 6, cc2 = idx & 63;
        float2 f = upk(g_Y[((size_t)((bh*16 + bb)*32 + r)*MY + ky)*CC + cc2]);
        sYre[cc2*20 + bb] = f.x;
        sYim[cc2*20 + bb] = f.y;
    }
    asm volatile("cp.async.wait_group 0;");
    __syncthreads();

    int o  = tid & 63;
    int bg = tid >> 6;                   // 4 groups, each 4 batches (2 pairs)
    u64 P1[2] = {0,0}, P2[2] = {0,0}, P3[2] = {0,0}, P4[2] = {0,0};

    for (int i = 0; i < 64; i++) {
        float wr = sWr[i*64 + o];
        float wi = sWi[i*64 + o];
        u64 wrp = pk(wr, wr);
        u64 wip = pk(wi, wi);
        ulonglong2 yr = *(const ulonglong2*)&sYre[i*20 + bg*4];
        ulonglong2 yi = *(const ulonglong2*)&sYim[i*20 + bg*4];
        fma2(P1[0], yr.x, wrp);  fma2(P2[0], yi.x, wip);
        fma2(P3[0], yr.x, wip);  fma2(P4[0], yi.x, wrp);
        fma2(P1[1], yr.y, wrp);  fma2(P2[1], yi.y, wip);
        fma2(P3[1], yr.y, wip);  fma2(P4[1], yi.y, wrp);
    }
#pragma unroll
    for (int bp = 0; bp < 2; bp++) {
        int bb = bh*16 + bg*4 + bp*2;
        float2 p1 = upk(P1[bp]), p2 = upk(P2[bp]);
        float2 p3 = upk(P3[bp]), p4 = upk(P4[bp]);
        g_G[((size_t)(bb    *MY + ky)*32 + r)*CC + o] = pk(p1.x - p2.x, p3.x + p4.x);
        g_G[((size_t)((bb+1)*MY + ky)*32 + r)*CC + o] = pk(p1.y - p2.y, p3.y + p4.y);
    }
}

// ---------------- stage D1: inverse DFT over h, r-pair + h-mirror symmetry ----------------
__global__ __launch_bounds__(512) void k_stageD1() {
    __shared__ __align__(16) u64 sG[32*64];
    __shared__ ulonglong2 sTP[128];
    int ky = blockIdx.x, b = blockIdx.y;
    int tid = threadIdx.x;
    for (int i = tid; i < 2048; i += 512)
        sG[i] = g_G[((size_t)(b*MY + ky)*32 + (i >> 6))*CC + (i & 63)];
    for (int i = tid; i < 128; i += 512) sTP[i] = g_TP[i];
    __syncthreads();

    int c  = tid & 63;
    int hg = tid >> 6;
    int hbase = 1 + hg*8;

    u64 mc[8], ms[8];
#pragma unroll
    for (int q = 0; q < 8; q++) { mc[q] = 0ull; ms[q] = 0ull; }
    u64 g0 = sG[c];
    u64 Ssum = 0ull;

#pragma unroll
    for (int r = 1; r <= 16; r++) {
        u64 S, Dp;
        if (r < 16) {
            float2 ga = upk(sG[r*64 + c]);
            float2 gb = upk(sG[(32 - r)*64 + c]);
            S  = pk(ga.x + gb.x, ga.y + gb.y);
            Dp = pk(gb.y - ga.y, ga.x - gb.x);
        } else {
            float2 g = upk(sG[16*64 + c]);
            S  = pk(g.x, g.y);
            Dp = pk(g.y, -g.x);
        }
        if (hg == 0) add2(Ssum, S);
        int mm = (r * hbase) & 127;
#pragma unroll
        for (int hh = 0; hh < 8; hh++) {
            ulonglong2 t = sTP[mm];
            fma2(mc[hh], S,  t.x);
            fma2(ms[hh], Dp, t.y);
            mm = (mm + r) & 127;
        }
    }

    float2 fg0 = upk(g0);
    size_t base = (size_t)(b*MY + ky)*HH;
#pragma unroll
    for (int hh = 0; hh < 8; hh++) {
        int h = hbase + hh;
        float2 c2 = upk(mc[hh]), s2 = upk(ms[hh]);
        float tre = fg0.x + c2.x, tim = fg0.y + c2.y;
        size_t off = (base + h)*CC + c;
        g_Mre[off] = tre + s2.x;
        g_Mim[off] = tim + s2.y;
        if (h < 64) {
            size_t off2 = (base + 128 - h)*CC + c;
            g_Mre[off2] = tre - s2.x;
            g_Mim[off2] = tim - s2.y;
        }
    }
    if (hg == 0) {
        float2 fs = upk(Ssum);
        size_t off = base*CC + c;
        g_Mre[off] = fg0.x + fs.x;
        g_Mim[off] = fg0.y + fs.y;
    }
}

// ---------------- stage E: full-row cp.async staging + 2-chain dense/spectral + GELU ----------------
// dynamic smem: xs2[4096] u64 | sTC[1024] u64 | sTS[1024] u64 = 49152 bytes
__global__ __launch_bounds__(256, 2) void k_stageE(const float* __restrict__ x,
                                                   const float* __restrict__ Kd,
                                                   const float* __restrict__ bias,
                                                   float* __restrict__ out) {
    extern __shared__ __align__(16) u64 dsm[];
    u64* xs2 = dsm;              // 4096 u64 = full 128-pixel row
    u64* sTC = dsm + 4096;       // 1024 u64
    u64* sTS = sTC + 1024;       // 1024 u64

    int h = blockIdx.x, b = blockIdx.y;
    int tid = threadIdx.x;
    int c  = tid & 63;
    int wg = tid >> 6;

    const float* xrow = x   + ((size_t)(b*HH + h)*WW)*CC;
    float*       orow = out + ((size_t)(b*HH + h)*WW)*CC;

    // fire-and-forget staging of x row + twiddle tables
    {
        unsigned sx = sptr(xs2);
#pragma unroll
        for (int j = 0; j < 8; j++) {
            int i = tid + j*256;
            CP16(sx + i*16, xrow + i*4);
        }
        unsigned stc = sptr(sTC), sts = sptr(sTS);
#pragma unroll
        for (int j = 0; j < 2; j++) {
            int i = tid + j*256;
            CP16(stc + i*16, (const float*)g_TC2 + i*4);
            CP16(sts + i*16, (const float*)g_TS2 + i*4);
        }
        asm volatile("cp.async.commit_group;");
    }

    // overlapped register prefetch: Kp, R2/I2, bias
    u64 Kp[32];
#pragma unroll
    for (int i = 0; i < 32; i++)
        Kp[i] = pk(Kd[(2*i)*64 + c], Kd[(2*i+1)*64 + c]);

    u64 R2[8], I2[8];
#pragma unroll
    for (int j = 0; j < 8; j++) {
        size_t o0 = ((size_t)(b*MY + 2*j    )*HH + h)*CC + c;
        size_t o1 = ((size_t)(b*MY + 2*j + 1)*HH + h)*CC + c;
        R2[j] = pk(g_Mre[o0], g_Mre[o1]);
        I2[j] = pk(g_Mim[o0], g_Mim[o1]);
    }
    float bc = bias[c];

    asm volatile("cp.async.wait_group 0;");
    __syncthreads();

    for (int ww = 0; ww < 32; ww++) {
        int w = wg*32 + ww;
        u64 acc0 = pk(bc, 0.f);
        u64 acc1 = 0ull;
        const ulonglong2* xv = (const ulonglong2*)&xs2[w*32];
#pragma unroll
        for (int t = 0; t < 16; t++) {
            ulonglong2 q = xv[t];
            fma2(acc0, q.x, Kp[2*t]);
            fma2(acc1, q.y, Kp[2*t + 1]);
        }
        const ulonglong2* tcp = (const ulonglong2*)&sTC[w*8];
        const ulonglong2* tsp = (const ulonglong2*)&sTS[w*8];
#pragma unroll
        for (int t = 0; t < 4; t++) {
            ulonglong2 tc = tcp[t];
            ulonglong2 ts = tsp[t];
            fma2(acc0, R2[2*t],     tc.x);
            fma2(acc1, R2[2*t + 1], tc.y);
            fma2(acc0, I2[2*t],     ts.x);
            fma2(acc1, I2[2*t + 1], ts.y);
        }
        float2 s0 = upk(acc0), s1 = upk(acc1);
        float xval = ((const float*)xs2)[w*64 + c];
        float u = xval + s0.x + s0.y + s1.x + s1.y;
        float u3 = u*u*u;
        float t = fast_tanh(0.7978845608028654f*(u + 0.044715f*u3));
        orow[(size_t)w*64 + c] = 0.5f*u*(1.f + t);
    }
}

// ---------------- launch ----------------
extern "C" void kernel_launch(void* const* d_in, const int* in_sizes, int n_in,
                              void* d_out, int out_size) {
    const float* x    = (const float*)d_in[0];
    const float* w1r  = (const float*)d_in[1];
    const float* w1i  = (const float*)d_in[2];
    const float* w2r  = (const float*)d_in[3];
    const float* w2i  = (const float*)d_in[4];
    const float* Kd   = (const float*)d_in[5];
    const float* bias = (const float*)d_in[6];
    float* out = (float*)d_out;

    const int A_SMEM = 1152*8 + 2*8192*4;                   // 9216 + 65536 = 74752 bytes
    const int C_SMEM = (4096 + 4096 + 64*20 + 64*20) * 4;   // 43008 bytes
    const int E_SMEM = (4096 + 1024 + 1024) * 8;            // 49152 bytes
    static int attr_set = 0;
    if (!attr_set) {
        cudaFuncSetAttribute(k_stageA, cudaFuncAttributeMaxDynamicSharedMemorySize, A_SMEM);
        cudaFuncSetAttribute(k_stageC, cudaFuncAttributeMaxDynamicSharedMemorySize, C_SMEM);
        cudaFuncSetAttribute(k_stageE, cudaFuncAttributeMaxDynamicSharedMemorySize, E_SMEM);
        attr_set = 1;
    }

    k_init<<<64, 256>>>();
    k_stageA<<<dim3(32, 32), 256, A_SMEM>>>(x);
    k_stageB<<<dim3(17, 32), 256>>>();
    k_stageC<<<dim3(16, 32, 2), 256, C_SMEM>>>(w1r, w1i, w2r, w2i);
    k_stageD1<<<dim3(16, 32), 512>>>();
    k_stageE<<<dim3(128, 32), 256, E_SMEM>>>(x, Kd, bias, out);
}

// round 15
// speedup vs baseline: 1.1693x; 1.0153x over previous
#include <cuda_runtime.h>
#include <math.h>

#define BB 32
#define HH 128
#define WW 128
#define CC 64
#define MX 16
#define MY 16
#define NK 17

typedef unsigned long long u64;

__device__ __forceinline__ u64 pk(float a, float b) {
    u64 r; asm("mov.b64 %0, {%1,%2};" : "=l"(r) : "f"(a), "f"(b)); return r;
}
__device__ __forceinline__ float2 upk(u64 v) {
    float2 f; asm("mov.b64 {%0,%1}, %2;" : "=f"(f.x), "=f"(f.y) : "l"(v)); return f;
}
__device__ __forceinline__ void fma2(u64 &d, u64 a, u64 b) {
    asm("fma.rn.f32x2 %0, %1, %2, %0;" : "+l"(d) : "l"(a), "l"(b));
}
__device__ __forceinline__ void add2(u64 &d, u64 a) {
    asm("add.rn.f32x2 %0, %0, %1;" : "+l"(d) : "l"(a));
}
__device__ __forceinline__ float fast_tanh(float x) {
    float t; asm("tanh.approx.f32 %0, %1;" : "=f"(t) : "f"(x)); return t;
}
__device__ __forceinline__ unsigned sptr(const void* p) {
    unsigned a;
    asm("{ .reg .u64 t; cvta.to.shared.u64 t, %1; cvt.u32.u64 %0, t; }" : "=r"(a) : "l"(p));
    return a;
}
#define CP16(s, g) asm volatile("cp.async.cg.shared.global [%0], [%1], 16;" :: "r"(s), "l"(g))

// ---------------- scratch ----------------
__device__ __align__(16) u64 g_X1[BB*NK*WW*CC];        // (re,im)
__device__ __align__(16) u64 g_Y [BB*32*MY*CC];        // (re,im)
__device__ __align__(16) u64 g_G [BB*MY*32*CC];        // (re,im) [b][ky][r][c]
__device__ __align__(16) float g_Mre[BB*MY*HH*CC];
__device__ __align__(16) float g_Mim[BB*MY*HH*CC];

// twiddle tables
__device__ __align__(16) u64 g_TA2[HH*18];             // [h][k] pk(cos,-sin), k=17 pad 0
__device__ __align__(16) u64 g_TBc[WW*MY];             // pk(c,c)
__device__ __align__(16) u64 g_TBs[WW*MY];             // pk(s,s)
__device__ __align__(16) ulonglong2 g_TP[128];         // {pk(c,c), pk(s,s)}
__device__ __align__(16) u64 g_TC2[WW*8];
__device__ __align__(16) u64 g_TS2[WW*8];

// ---------------- init ----------------
__global__ void k_init() {
    int t = blockIdx.x * blockDim.x + threadIdx.x;
    int stride = gridDim.x * blockDim.x;
    const float STEP = 6.28318530717958647692f / 128.0f;

    for (int i = t; i < HH*18; i += stride) {
        int h = i / 18, k = i % 18;
        if (k < 17) {
            int m = (k * h) & 127;
            float s, c; sincosf(STEP * (float)m, &s, &c);
            g_TA2[i] = pk(c, -s);
        } else g_TA2[i] = 0ull;
    }
    for (int i = t; i < WW*MY; i += stride) {
        int w = i / MY, ky = i % MY;
        int m = (ky * w) & 127;
        float s, c; sincosf(STEP * (float)m, &s, &c);
        g_TBc[i] = pk(c, c);
        g_TBs[i] = pk(s, s);
    }
    for (int i = t; i < 128; i += stride) {
        float s, c; sincosf(STEP * (float)i, &s, &c);
        g_TP[i].x = pk(c, c);
        g_TP[i].y = pk(s, s);
    }
    for (int i = t; i < WW*8; i += stride) {
        int w = i / 8, j = i % 8;
        int k0 = 2*j, k1 = 2*j + 1;
        float s0, c0, s1, c1;
        sincosf(STEP * (float)((k0 * w) & 127), &s0, &c0);
        sincosf(STEP * (float)((k1 * w) & 127), &s1, &c1);
        float f0 = ((k0 == 0) ? 1.f : 2.f) / 16384.f;
        float f1 = 2.f / 16384.f;
        g_TC2[i] = pk(f0 * c0, f1 * c1);
        g_TS2[i] = pk(-f0 * s0, -f1 * s1);
    }
}

// ---------------- stage A: partial DFT over h, h-pair symmetry, cp.async chunked staging ----------------
// dynamic smem: sTA[576 ulonglong2 = 9216B] | buf[2][8192 floats]
__global__ __launch_bounds__(256, 2) void k_stageA(const float* __restrict__ x) {
    extern __shared__ __align__(16) u64 adsm[];
    ulonglong2* sTA = (ulonglong2*)adsm;          // 64*9 = 576 entries
    float* buf = (float*)(adsm + 1152);           // 2 * 8192 floats

    int b = blockIdx.y, wt = blockIdx.x;
    int tid = threadIdx.x;
    for (int i = tid; i < 576; i += 256) sTA[i] = ((const ulonglong2*)g_TA2)[i];

    const float* xb0 = x + (size_t)b * HH * WW * CC + (size_t)(wt*4) * CC;

    auto issue = [&](int ci, int s) {
        unsigned sb = sptr(buf + s*8192);
        int p0 = 1 + 16*ci;
#pragma unroll
        for (int t = 0; t < 4; t++) {
            int idx = tid + t*256;            // 0..1023
            int j = idx >> 6, q = idx & 63;   // row j, 16B chunk q
            CP16(sb + j*1024 + q*16,         xb0 + (size_t)(p0 + j)*WW*CC + q*4);
            CP16(sb + 16384 + j*1024 + q*16, xb0 + (size_t)(128 - p0 - j)*WW*CC + q*4);
        }
        asm volatile("cp.async.commit_group;");
    };

    issue(0, 0);
    issue(1, 1);

    int c  = tid & 63;
    int wl = tid >> 6;
    int w  = wt*4 + wl;
    const float* xb = xb0 + (size_t)wl*CC + c;

    u64 a[18];
    {   // h = 0 and h = 64 singles (overlapped with cp.async)
        float x0  = xb[0];
        float x64 = xb[(size_t)64*WW*CC];
        float ep = x0 + x64, em = x0 - x64;
#pragma unroll
        for (int k = 0; k < 17; k++) a[k] = pk((k & 1) ? em : ep, 0.f);
        a[17] = 0ull;
    }

    for (int ci = 0; ci < 4; ci++) {
        if (ci < 3) asm volatile("cp.async.wait_group 1;");
        else        asm volatile("cp.async.wait_group 0;");
        __syncthreads();

        int s = ci & 1;
        const float* lo = buf + s*8192 + wl*64 + c;
        const float* hi = lo + 4096;
        int p0 = 1 + 16*ci;
        int npairs = (ci < 3) ? 16 : 15;
        for (int j = 0; j < npairs; j++) {
            float va = lo[j*256];
            float vb = hi[j*256];
            u64 sd = pk(va + vb, va - vb);
            const ulonglong2* tw = &sTA[(p0 + j)*9];
#pragma unroll
            for (int q = 0; q < 9; q++) {
                ulonglong2 t = tw[q];
                fma2(a[2*q],   sd, t.x);
                fma2(a[2*q+1], sd, t.y);
            }
        }
        __syncthreads();
        if (ci < 2) issue(ci + 2, s);
    }

#pragma unroll
    for (int k = 0; k < 17; k++)
        g_X1[((size_t)(b*NK + k)*WW + w)*CC + c] = a[k];
}

// ---------------- stage B: partial DFT over w, w-pair symmetry, cp.async chunked staging ----------------
// static smem: sCC/sSS (16KB); dynamic smem: buf[2][2048 u64] = 32KB
__global__ __launch_bounds__(256) void k_stageB() {
    __shared__ __align__(16) u64 sCC[64*MY];
    __shared__ __align__(16) u64 sSS[64*MY];
    extern __shared__ __align__(16) u64 bdsm[];   // 2 * 2048 u64 (16KB each)

    int b = blockIdx.y, k = blockIdx.x;   // 0..16
    int tid = threadIdx.x;
    for (int i = tid; i < 64*MY; i += 256) { sCC[i] = g_TBc[i]; sSS[i] = g_TBs[i]; }

    const u64* xp = g_X1 + (size_t)(b*NK + k)*WW*CC;
    const float* xf = (const float*)xp;

    // chunk ci covers pairs w = 1+16ci .. 16+16ci
    // low rows w at buf[s][0..1023], high rows 128-w at buf[s][1024..2047] (u64 units)
    auto issue = [&](int ci, int s) {
        unsigned sb = sptr(bdsm + (size_t)s*2048);
        int p0 = 1 + 16*ci;
#pragma unroll
        for (int t = 0; t < 2; t++) {
            int idx = tid + t*256;            // 0..511
            int j = idx >> 5, q = idx & 31;   // row j (0..15), 16B chunk q (0..31)
            CP16(sb + j*512 + q*16,        xf + (size_t)(p0 + j)*128 + q*4);
            CP16(sb + 8192 + j*512 + q*16, xf + (size_t)(128 - p0 - j)*128 + q*4);
        }
        asm volatile("cp.async.commit_group;");
    };

    issue(0, 0);
    issue(1, 1);

    int c  = tid & 63;
    int kg = tid >> 6;

    u64 P[4], Q[4] = {0,0,0,0};
    {   // w = 0 and w = 64 singles (sin = 0) — overlapped with cp.async
        float2 f0  = upk(xp[c]);
        float2 f64 = upk(xp[64*CC + c]);
#pragma unroll
        for (int j = 0; j < 4; j++) {
            int ky = kg*4 + j;
            float sx = (ky & 1) ? -f64.x : f64.x;
            float sy = (ky & 1) ? -f64.y : f64.y;
            P[j] = pk(f0.x + sx, f0.y + sy);
        }
    }

    for (int ci = 0; ci < 4; ci++) {
        if (ci < 3) asm volatile("cp.async.wait_group 1;");
        else        asm volatile("cp.async.wait_group 0;");
        __syncthreads();

        int s = ci & 1;
        const u64* lo = bdsm + (size_t)s*2048 + c;
        const u64* hi = lo + 1024;
        int p0 = 1 + 16*ci;
        int npairs = (ci < 3) ? 16 : 15;      // chunk 3: w = 49..63
        for (int j = 0; j < npairs; j++) {
            float2 fa = upk(lo[j*64]);
            float2 fb = upk(hi[j*64]);
            u64 Vs  = pk(fa.x + fb.x, fa.y + fb.y);
            u64 VdA = pk(fa.y - fb.y, fb.x - fa.x);
            int w = p0 + j;
            const ulonglong2* cp = (const ulonglong2*)&sCC[w*MY + kg*4];
            const ulonglong2* sp = (const ulonglong2*)&sSS[w*MY + kg*4];
            ulonglong2 c01 = cp[0], c23 = cp[1];
            ulonglong2 s01 = sp[0], s23 = sp[1];
            fma2(P[0], Vs, c01.x);  fma2(Q[0], VdA, s01.x);
            fma2(P[1], Vs, c01.y);  fma2(Q[1], VdA, s01.y);
            fma2(P[2], Vs, c23.x);  fma2(Q[2], VdA, s23.x);
            fma2(P[3], Vs, c23.y);  fma2(Q[3], VdA, s23.y);
        }
        __syncthreads();
        if (ci < 2) issue(ci + 2, s);
    }

    if (k < 16) {
#pragma unroll
        for (int j = 0; j < 4; j++) {
            int ky = kg*4 + j;
            float2 p = upk(P[j]), q = upk(Q[j]);
            g_Y[((size_t)(b*32 + k)*MY + ky)*CC + c] = pk(p.x + q.x, p.y + q.y);
        }
    }
    if (k >= 1) {
        int r2 = 32 - k;
#pragma unroll
        for (int j = 0; j < 4; j++) {
            int ky = kg*4 + j;
            float2 p = upk(P[j]), q = upk(Q[j]);
            g_Y[((size_t)(b*32 + r2)*MY + ky)*CC + c] = pk(p.x - q.x, q.y - p.y);
        }
    }
}

// ---------------- stage C: complex mode mixing, cp.async W staging, batch-split 2x ----------------
__global__ __launch_bounds__(256) void k_stageC(const float* __restrict__ w1r,
                                                const float* __restrict__ w1i,
                                                const float* __restrict__ w2r,
                                                const float* __restrict__ w2i) {
    extern __shared__ __align__(16) float smem[];
    float* sWr  = smem;
    float* sWi  = smem + 4096;
    float* sYre = smem + 8192;
    float* sYim = sYre + 64*20;

    int ky = blockIdx.x, r = blockIdx.y;
    int bh = blockIdx.z;                 // batch half: 0 or 1
    int tid = threadIdx.x;

    const float* __restrict__ Wr;
    const float* __restrict__ Wi;
    if (r < 16) {
        Wr = w1r + (size_t)((r*16 + ky)*64)*64;
        Wi = w1i + (size_t)((r*16 + ky)*64)*64;
    } else {
        Wr = w2r + (size_t)(((r-16)*16 + ky)*64)*64;
        Wi = w2i + (size_t)(((r-16)*16 + ky)*64)*64;
    }

    {
        unsigned swr = sptr(sWr), swi = sptr(sWi);
#pragma unroll
        for (int j = 0; j < 4; j++) {
            int i = tid + j*256;
            CP16(swr + i*16, Wr + i*4);
            CP16(swi + i*16, Wi + i*4);
        }
        asm volatile("cp.async.commit_group;");
    }

    // Y transpose: 16 batches x 64 channels
    for (int idx = tid; idx < 1024; idx += 256) {
        int bb = idx >> 6, cc2 = idx & 63;
        float2 f = upk(g_Y[((size_t)((bh*16 + bb)*32 + r)*MY + ky)*CC + cc2]);
        sYre[cc2*20 + bb] = f.x;
        sYim[cc2*20 + bb] = f.y;
    }
    asm volatile("cp.async.wait_group 0;");
    __syncthreads();

    int o  = tid & 63;
    int bg = tid >> 6;                   // 4 groups, each 4 batches (2 pairs)
    u64 P1[2] = {0,0}, P2[2] = {0,0}, P3[2] = {0,0}, P4[2] = {0,0};

    for (int i = 0; i < 64; i++) {
        float wr = sWr[i*64 + o];
        float wi = sWi[i*64 + o];
        u64 wrp = pk(wr, wr);
        u64 wip = pk(wi, wi);
        ulonglong2 yr = *(const ulonglong2*)&sYre[i*20 + bg*4];
        ulonglong2 yi = *(const ulonglong2*)&sYim[i*20 + bg*4];
        fma2(P1[0], yr.x, wrp);  fma2(P2[0], yi.x, wip);
        fma2(P3[0], yr.x, wip);  fma2(P4[0], yi.x, wrp);
        fma2(P1[1], yr.y, wrp);  fma2(P2[1], yi.y, wip);
        fma2(P3[1], yr.y, wip);  fma2(P4[1], yi.y, wrp);
    }
#pragma unroll
    for (int bp = 0; bp < 2; bp++) {
        int bb = bh*16 + bg*4 + bp*2;
        float2 p1 = upk(P1[bp]), p2 = upk(P2[bp]);
        float2 p3 = upk(P3[bp]), p4 = upk(P4[bp]);
        g_G[((size_t)(bb    *MY + ky)*32 + r)*CC + o] = pk(p1.x - p2.x, p3.x + p4.x);
        g_G[((size_t)((bb+1)*MY + ky)*32 + r)*CC + o] = pk(p1.y - p2.y, p3.y + p4.y);
    }
}

// ---------------- stage D1: inverse DFT over h, r-pair + h-mirror symmetry ----------------
__global__ __launch_bounds__(512) void k_stageD1() {
    __shared__ __align__(16) u64 sG[32*64];
    __shared__ ulonglong2 sTP[128];
    int ky = blockIdx.x, b = blockIdx.y;
    int tid = threadIdx.x;
    for (int i = tid; i < 2048; i += 512)
        sG[i] = g_G[((size_t)(b*MY + ky)*32 + (i >> 6))*CC + (i & 63)];
    for (int i = tid; i < 128; i += 512) sTP[i] = g_TP[i];
    __syncthreads();

    int c  = tid & 63;
    int hg = tid >> 6;
    int hbase = 1 + hg*8;

    u64 mc[8], ms[8];
#pragma unroll
    for (int q = 0; q < 8; q++) { mc[q] = 0ull; ms[q] = 0ull; }
    u64 g0 = sG[c];
    u64 Ssum = 0ull;

#pragma unroll
    for (int r = 1; r <= 16; r++) {
        u64 S, Dp;
        if (r < 16) {
            float2 ga = upk(sG[r*64 + c]);
            float2 gb = upk(sG[(32 - r)*64 + c]);
            S  = pk(ga.x + gb.x, ga.y + gb.y);
            Dp = pk(gb.y - ga.y, ga.x - gb.x);
        } else {
            float2 g = upk(sG[16*64 + c]);
            S  = pk(g.x, g.y);
            Dp = pk(g.y, -g.x);
        }
        if (hg == 0) add2(Ssum, S);
        int mm = (r * hbase) & 127;
#pragma unroll
        for (int hh = 0; hh < 8; hh++) {
            ulonglong2 t = sTP[mm];
            fma2(mc[hh], S,  t.x);
            fma2(ms[hh], Dp, t.y);
            mm = (mm + r) & 127;
        }
    }

    float2 fg0 = upk(g0);
    size_t base = (size_t)(b*MY + ky)*HH;
#pragma unroll
    for (int hh = 0; hh < 8; hh++) {
        int h = hbase + hh;
        float2 c2 = upk(mc[hh]), s2 = upk(ms[hh]);
        float tre = fg0.x + c2.x, tim = fg0.y + c2.y;
        size_t off = (base + h)*CC + c;
        g_Mre[off] = tre + s2.x;
        g_Mim[off] = tim + s2.y;
        if (h < 64) {
            size_t off2 = (base + 128 - h)*CC + c;
            g_Mre[off2] = tre - s2.x;
            g_Mim[off2] = tim - s2.y;
        }
    }
    if (hg == 0) {
        float2 fs = upk(Ssum);
        size_t off = base*CC + c;
        g_Mre[off] = fg0.x + fs.x;
        g_Mim[off] = fg0.y + fs.y;
    }
}

// ---------------- stage E: full-row cp.async staging + 2-chain dense/spectral + GELU ----------------
// dynamic smem: xs2[4096] u64 | sTC[1024] u64 | sTS[1024] u64 = 49152 bytes
__global__ __launch_bounds__(256, 2) void k_stageE(const float* __restrict__ x,
                                                   const float* __restrict__ Kd,
                                                   const float* __restrict__ bias,
                                                   float* __restrict__ out) {
    extern __shared__ __align__(16) u64 dsm[];
    u64* xs2 = dsm;              // 4096 u64 = full 128-pixel row
    u64* sTC = dsm + 4096;       // 1024 u64
    u64* sTS = sTC + 1024;       // 1024 u64

    int h = blockIdx.x, b = blockIdx.y;
    int tid = threadIdx.x;
    int c  = tid & 63;
    int wg = tid >> 6;

    const float* xrow = x   + ((size_t)(b*HH + h)*WW)*CC;
    float*       orow = out + ((size_t)(b*HH + h)*WW)*CC;

    // fire-and-forget staging of x row + twiddle tables
    {
        unsigned sx = sptr(xs2);
#pragma unroll
        for (int j = 0; j < 8; j++) {
            int i = tid + j*256;
            CP16(sx + i*16, xrow + i*4);
        }
        unsigned stc = sptr(sTC), sts = sptr(sTS);
#pragma unroll
        for (int j = 0; j < 2; j++) {
            int i = tid + j*256;
            CP16(stc + i*16, (const float*)g_TC2 + i*4);
            CP16(sts + i*16, (const float*)g_TS2 + i*4);
        }
        asm volatile("cp.async.commit_group;");
    }

    // overlapped register prefetch: Kp, R2/I2, bias
    u64 Kp[32];
#pragma unroll
    for (int i = 0; i < 32; i++)
        Kp[i] = pk(Kd[(2*i)*64 + c], Kd[(2*i+1)*64 + c]);

    u64 R2[8], I2[8];
#pragma unroll
    for (int j = 0; j < 8; j++) {
        size_t o0 = ((size_t)(b*MY + 2*j    )*HH + h)*CC + c;
        size_t o1 = ((size_t)(b*MY + 2*j + 1)*HH + h)*CC + c;
        R2[j] = pk(g_Mre[o0], g_Mre[o1]);
        I2[j] = pk(g_Mim[o0], g_Mim[o1]);
    }
    float bc = bias[c];

    asm volatile("cp.async.wait_group 0;");
    __syncthreads();

    for (int ww = 0; ww < 32; ww++) {
        int w = wg*32 + ww;
        u64 acc0 = pk(bc, 0.f);
        u64 acc1 = 0ull;
        const ulonglong2* xv = (const ulonglong2*)&xs2[w*32];
#pragma unroll
        for (int t = 0; t < 16; t++) {
            ulonglong2 q = xv[t];
            fma2(acc0, q.x, Kp[2*t]);
            fma2(acc1, q.y, Kp[2*t + 1]);
        }
        const ulonglong2* tcp = (const ulonglong2*)&sTC[w*8];
        const ulonglong2* tsp = (const ulonglong2*)&sTS[w*8];
#pragma unroll
        for (int t = 0; t < 4; t++) {
            ulonglong2 tc = tcp[t];
            ulonglong2 ts = tsp[t];
            fma2(acc0, R2[2*t],     tc.x);
            fma2(acc1, R2[2*t + 1], tc.y);
            fma2(acc0, I2[2*t],     ts.x);
            fma2(acc1, I2[2*t + 1], ts.y);
        }
        float2 s0 = upk(acc0), s1 = upk(acc1);
        float xval = ((const float*)xs2)[w*64 + c];
        float u = xval + s0.x + s0.y + s1.x + s1.y;
        float u3 = u*u*u;
        float t = fast_tanh(0.7978845608028654f*(u + 0.044715f*u3));
        orow[(size_t)w*64 + c] = 0.5f*u*(1.f + t);
    }
}

// ---------------- launch ----------------
extern "C" void kernel_launch(void* const* d_in, const int* in_sizes, int n_in,
                              void* d_out, int out_size) {
    const float* x    = (const float*)d_in[0];
    const float* w1r  = (const float*)d_in[1];
    const float* w1i  = (const float*)d_in[2];
    const float* w2r  = (const float*)d_in[3];
    const float* w2i  = (const float*)d_in[4];
    const float* Kd   = (const float*)d_in[5];
    const float* bias = (const float*)d_in[6];
    float* out = (float*)d_out;

    const int A_SMEM = 1152*8 + 2*8192*4;                   // 74752 bytes
    const int B_SMEM = 2*2048*8;                            // 32768 bytes dynamic
    const int C_SMEM = (4096 + 4096 + 64*20 + 64*20) * 4;   // 43008 bytes
    const int E_SMEM = (4096 + 1024 + 1024) * 8;            // 49152 bytes
    static int attr_set = 0;
    if (!attr_set) {
        cudaFuncSetAttribute(k_stageA, cudaFuncAttributeMaxDynamicSharedMemorySize, A_SMEM);
        cudaFuncSetAttribute(k_stageB, cudaFuncAttributeMaxDynamicSharedMemorySize, B_SMEM);
        cudaFuncSetAttribute(k_stageC, cudaFuncAttributeMaxDynamicSharedMemorySize, C_SMEM);
        cudaFuncSetAttribute(k_stageE, cudaFuncAttributeMaxDynamicSharedMemorySize, E_SMEM);
        attr_set = 1;
    }

    k_init<<<64, 256>>>();
    k_stageA<<<dim3(32, 32), 256, A_SMEM>>>(x);
    k_stageB<<<dim3(17, 32), 256, B_SMEM>>>();
    k_stageC<<<dim3(16, 32, 2), 256, C_SMEM>>>(w1r, w1i, w2r, w2i);
    k_stageD1<<<dim3(16, 32), 512>>>();
    k_stageE<<<dim3(128, 32), 256, E_SMEM>>>(x, Kd, bias, out);
}

// round 16
// speedup vs baseline: 1.1968x; 1.0235x over previous
#include <cuda_runtime.h>
#include <math.h>

#define BB 32
#define HH 128
#define WW 128
#define CC 64
#define MX 16
#define MY 16
#define NK 17

typedef unsigned long long u64;

__device__ __forceinline__ u64 pk(float a, float b) {
    u64 r; asm("mov.b64 %0, {%1,%2};" : "=l"(r) : "f"(a), "f"(b)); return r;
}
__device__ __forceinline__ float2 upk(u64 v) {
    float2 f; asm("mov.b64 {%0,%1}, %2;" : "=f"(f.x), "=f"(f.y) : "l"(v)); return f;
}
__device__ __forceinline__ void fma2(u64 &d, u64 a, u64 b) {
    asm("fma.rn.f32x2 %0, %1, %2, %0;" : "+l"(d) : "l"(a), "l"(b));
}
__device__ __forceinline__ void add2(u64 &d, u64 a) {
    asm("add.rn.f32x2 %0, %0, %1;" : "+l"(d) : "l"(a));
}
__device__ __forceinline__ float fast_tanh(float x) {
    float t; asm("tanh.approx.f32 %0, %1;" : "=f"(t) : "f"(x)); return t;
}
__device__ __forceinline__ unsigned sptr(const void* p) {
    unsigned a;
    asm("{ .reg .u64 t; cvta.to.shared.u64 t, %1; cvt.u32.u64 %0, t; }" : "=r"(a) : "l"(p));
    return a;
}
#define CP16(s, g) asm volatile("cp.async.cg.shared.global [%0], [%1], 16;" :: "r"(s), "l"(g))

// ---------------- scratch ----------------
__device__ __align__(16) u64 g_X1[BB*NK*WW*CC];        // (re,im)
__device__ __align__(16) u64 g_Y [BB*32*MY*CC];        // (re,im)
__device__ __align__(16) u64 g_G [BB*MY*32*CC];        // (re,im) [b][ky][r][c]
__device__ __align__(16) float g_Mre[BB*MY*HH*CC];
__device__ __align__(16) float g_Mim[BB*MY*HH*CC];

// twiddle tables
__device__ __align__(16) u64 g_TA2[HH*18];             // [h][k] pk(cos,-sin), k=17 pad 0
__device__ __align__(16) u64 g_TBc[WW*MY];             // pk(c,c)
__device__ __align__(16) u64 g_TBs[WW*MY];             // pk(s,s)
__device__ __align__(16) ulonglong2 g_TP[128];         // {pk(c,c), pk(s,s)}
__device__ __align__(16) u64 g_TC2[WW*8];
__device__ __align__(16) u64 g_TS2[WW*8];

// ---------------- init ----------------
__global__ void k_init() {
    int t = blockIdx.x * blockDim.x + threadIdx.x;
    int stride = gridDim.x * blockDim.x;
    const float STEP = 6.28318530717958647692f / 128.0f;

    for (int i = t; i < HH*18; i += stride) {
        int h = i / 18, k = i % 18;
        if (k < 17) {
            int m = (k * h) & 127;
            float s, c; sincosf(STEP * (float)m, &s, &c);
            g_TA2[i] = pk(c, -s);
        } else g_TA2[i] = 0ull;
    }
    for (int i = t; i < WW*MY; i += stride) {
        int w = i / MY, ky = i % MY;
        int m = (ky * w) & 127;
        float s, c; sincosf(STEP * (float)m, &s, &c);
        g_TBc[i] = pk(c, c);
        g_TBs[i] = pk(s, s);
    }
    for (int i = t; i < 128; i += stride) {
        float s, c; sincosf(STEP * (float)i, &s, &c);
        g_TP[i].x = pk(c, c);
        g_TP[i].y = pk(s, s);
    }
    for (int i = t; i < WW*8; i += stride) {
        int w = i / 8, j = i % 8;
        int k0 = 2*j, k1 = 2*j + 1;
        float s0, c0, s1, c1;
        sincosf(STEP * (float)((k0 * w) & 127), &s0, &c0);
        sincosf(STEP * (float)((k1 * w) & 127), &s1, &c1);
        float f0 = ((k0 == 0) ? 1.f : 2.f) / 16384.f;
        float f1 = 2.f / 16384.f;
        g_TC2[i] = pk(f0 * c0, f1 * c1);
        g_TS2[i] = pk(-f0 * s0, -f1 * s1);
    }
}

// ---------------- stage A: partial DFT over h, h-pair symmetry, cp.async chunked staging ----------------
__global__ __launch_bounds__(256, 2) void k_stageA(const float* __restrict__ x) {
    extern __shared__ __align__(16) u64 adsm[];
    ulonglong2* sTA = (ulonglong2*)adsm;          // 64*9 = 576 entries
    float* buf = (float*)(adsm + 1152);           // 2 * 8192 floats

    int b = blockIdx.y, wt = blockIdx.x;
    int tid = threadIdx.x;
    for (int i = tid; i < 576; i += 256) sTA[i] = ((const ulonglong2*)g_TA2)[i];

    const float* xb0 = x + (size_t)b * HH * WW * CC + (size_t)(wt*4) * CC;

    auto issue = [&](int ci, int s) {
        unsigned sb = sptr(buf + s*8192);
        int p0 = 1 + 16*ci;
#pragma unroll
        for (int t = 0; t < 4; t++) {
            int idx = tid + t*256;
            int j = idx >> 6, q = idx & 63;
            CP16(sb + j*1024 + q*16,         xb0 + (size_t)(p0 + j)*WW*CC + q*4);
            CP16(sb + 16384 + j*1024 + q*16, xb0 + (size_t)(128 - p0 - j)*WW*CC + q*4);
        }
        asm volatile("cp.async.commit_group;");
    };

    issue(0, 0);
    issue(1, 1);

    int c  = tid & 63;
    int wl = tid >> 6;
    int w  = wt*4 + wl;
    const float* xb = xb0 + (size_t)wl*CC + c;

    u64 a[18];
    {
        float x0  = xb[0];
        float x64 = xb[(size_t)64*WW*CC];
        float ep = x0 + x64, em = x0 - x64;
#pragma unroll
        for (int k = 0; k < 17; k++) a[k] = pk((k & 1) ? em : ep, 0.f);
        a[17] = 0ull;
    }

    for (int ci = 0; ci < 4; ci++) {
        if (ci < 3) asm volatile("cp.async.wait_group 1;");
        else        asm volatile("cp.async.wait_group 0;");
        __syncthreads();

        int s = ci & 1;
        const float* lo = buf + s*8192 + wl*64 + c;
        const float* hi = lo + 4096;
        int p0 = 1 + 16*ci;
        int npairs = (ci < 3) ? 16 : 15;
        for (int j = 0; j < npairs; j++) {
            float va = lo[j*256];
            float vb = hi[j*256];
            u64 sd = pk(va + vb, va - vb);
            const ulonglong2* tw = &sTA[(p0 + j)*9];
#pragma unroll
            for (int q = 0; q < 9; q++) {
                ulonglong2 t = tw[q];
                fma2(a[2*q],   sd, t.x);
                fma2(a[2*q+1], sd, t.y);
            }
        }
        __syncthreads();
        if (ci < 2) issue(ci + 2, s);
    }

#pragma unroll
    for (int k = 0; k < 17; k++)
        g_X1[((size_t)(b*NK + k)*WW + w)*CC + c] = a[k];
}

// ---------------- stage B: partial DFT over w, w-pair symmetry, cp.async chunked staging ----------------
__global__ __launch_bounds__(256) void k_stageB() {
    __shared__ __align__(16) u64 sCC[64*MY];
    __shared__ __align__(16) u64 sSS[64*MY];
    extern __shared__ __align__(16) u64 bdsm[];   // 2 * 2048 u64

    int b = blockIdx.y, k = blockIdx.x;   // 0..16
    int tid = threadIdx.x;
    for (int i = tid; i < 64*MY; i += 256) { sCC[i] = g_TBc[i]; sSS[i] = g_TBs[i]; }

    const u64* xp = g_X1 + (size_t)(b*NK + k)*WW*CC;
    const float* xf = (const float*)xp;

    auto issue = [&](int ci, int s) {
        unsigned sb = sptr(bdsm + (size_t)s*2048);
        int p0 = 1 + 16*ci;
#pragma unroll
        for (int t = 0; t < 2; t++) {
            int idx = tid + t*256;
            int j = idx >> 5, q = idx & 31;
            CP16(sb + j*512 + q*16,        xf + (size_t)(p0 + j)*128 + q*4);
            CP16(sb + 8192 + j*512 + q*16, xf + (size_t)(128 - p0 - j)*128 + q*4);
        }
        asm volatile("cp.async.commit_group;");
    };

    issue(0, 0);
    issue(1, 1);

    int c  = tid & 63;
    int kg = tid >> 6;

    u64 P[4], Q[4] = {0,0,0,0};
    {
        float2 f0  = upk(xp[c]);
        float2 f64 = upk(xp[64*CC + c]);
#pragma unroll
        for (int j = 0; j < 4; j++) {
            int ky = kg*4 + j;
            float sx = (ky & 1) ? -f64.x : f64.x;
            float sy = (ky & 1) ? -f64.y : f64.y;
            P[j] = pk(f0.x + sx, f0.y + sy);
        }
    }

    for (int ci = 0; ci < 4; ci++) {
        if (ci < 3) asm volatile("cp.async.wait_group 1;");
        else        asm volatile("cp.async.wait_group 0;");
        __syncthreads();

        int s = ci & 1;
        const u64* lo = bdsm + (size_t)s*2048 + c;
        const u64* hi = lo + 1024;
        int p0 = 1 + 16*ci;
        int npairs = (ci < 3) ? 16 : 15;
        for (int j = 0; j < npairs; j++) {
            float2 fa = upk(lo[j*64]);
            float2 fb = upk(hi[j*64]);
            u64 Vs  = pk(fa.x + fb.x, fa.y + fb.y);
            u64 VdA = pk(fa.y - fb.y, fb.x - fa.x);
            int w = p0 + j;
            const ulonglong2* cp = (const ulonglong2*)&sCC[w*MY + kg*4];
            const ulonglong2* sp = (const ulonglong2*)&sSS[w*MY + kg*4];
            ulonglong2 c01 = cp[0], c23 = cp[1];
            ulonglong2 s01 = sp[0], s23 = sp[1];
            fma2(P[0], Vs, c01.x);  fma2(Q[0], VdA, s01.x);
            fma2(P[1], Vs, c01.y);  fma2(Q[1], VdA, s01.y);
            fma2(P[2], Vs, c23.x);  fma2(Q[2], VdA, s23.x);
            fma2(P[3], Vs, c23.y);  fma2(Q[3], VdA, s23.y);
        }
        __syncthreads();
        if (ci < 2) issue(ci + 2, s);
    }

    if (k < 16) {
#pragma unroll
        for (int j = 0; j < 4; j++) {
            int ky = kg*4 + j;
            float2 p = upk(P[j]), q = upk(Q[j]);
            g_Y[((size_t)(b*32 + k)*MY + ky)*CC + c] = pk(p.x + q.x, p.y + q.y);
        }
    }
    if (k >= 1) {
        int r2 = 32 - k;
#pragma unroll
        for (int j = 0; j < 4; j++) {
            int ky = kg*4 + j;
            float2 p = upk(P[j]), q = upk(Q[j]);
            g_Y[((size_t)(b*32 + r2)*MY + ky)*CC + c] = pk(p.x - q.x, q.y - p.y);
        }
    }
}

// ---------------- stage C: complex mode mixing, cp.async W staging, batch-split 2x ----------------
__global__ __launch_bounds__(256) void k_stageC(const float* __restrict__ w1r,
                                                const float* __restrict__ w1i,
                                                const float* __restrict__ w2r,
                                                const float* __restrict__ w2i) {
    extern __shared__ __align__(16) float smem[];
    float* sWr  = smem;
    float* sWi  = smem + 4096;
    float* sYre = smem + 8192;
    float* sYim = sYre + 64*20;

    int ky = blockIdx.x, r = blockIdx.y;
    int bh = blockIdx.z;
    int tid = threadIdx.x;

    const float* __restrict__ Wr;
    const float* __restrict__ Wi;
    if (r < 16) {
        Wr = w1r + (size_t)((r*16 + ky)*64)*64;
        Wi = w1i + (size_t)((r*16 + ky)*64)*64;
    } else {
        Wr = w2r + (size_t)(((r-16)*16 + ky)*64)*64;
        Wi = w2i + (size_t)(((r-16)*16 + ky)*64)*64;
    }

    {
        unsigned swr = sptr(sWr), swi = sptr(sWi);
#pragma unroll
        for (int j = 0; j < 4; j++) {
            int i = tid + j*256;
            CP16(swr + i*16, Wr + i*4);
            CP16(swi + i*16, Wi + i*4);
        }
        asm volatile("cp.async.commit_group;");
    }

    for (int idx = tid; idx < 1024; idx += 256) {
        int bb = idx >> 6, cc2 = idx & 63;
        float2 f = upk(g_Y[((size_t)((bh*16 + bb)*32 + r)*MY + ky)*CC + cc2]);
        sYre[cc2*20 + bb] = f.x;
        sYim[cc2*20 + bb] = f.y;
    }
    asm volatile("cp.async.wait_group 0;");
    __syncthreads();

    int o  = tid & 63;
    int bg = tid >> 6;
    u64 P1[2] = {0,0}, P2[2] = {0,0}, P3[2] = {0,0}, P4[2] = {0,0};

    for (int i = 0; i < 64; i++) {
        float wr = sWr[i*64 + o];
        float wi = sWi[i*64 + o];
        u64 wrp = pk(wr, wr);
        u64 wip = pk(wi, wi);
        ulonglong2 yr = *(const ulonglong2*)&sYre[i*20 + bg*4];
        ulonglong2 yi = *(const ulonglong2*)&sYim[i*20 + bg*4];
        fma2(P1[0], yr.x, wrp);  fma2(P2[0], yi.x, wip);
        fma2(P3[0], yr.x, wip);  fma2(P4[0], yi.x, wrp);
        fma2(P1[1], yr.y, wrp);  fma2(P2[1], yi.y, wip);
        fma2(P3[1], yr.y, wip);  fma2(P4[1], yi.y, wrp);
    }
#pragma unroll
    for (int bp = 0; bp < 2; bp++) {
        int bb = bh*16 + bg*4 + bp*2;
        float2 p1 = upk(P1[bp]), p2 = upk(P2[bp]);
        float2 p3 = upk(P3[bp]), p4 = upk(P4[bp]);
        g_G[((size_t)(bb    *MY + ky)*32 + r)*CC + o] = pk(p1.x - p2.x, p3.x + p4.x);
        g_G[((size_t)((bb+1)*MY + ky)*32 + r)*CC + o] = pk(p1.y - p2.y, p3.y + p4.y);
    }
}

// ---------------- stage D1: inverse DFT over h, c-split + cp.async staging ----------------
// grid (16, 32, 2): ky, b, channel-half. dynamic smem: sG[32*32 u64] = 8KB
__global__ __launch_bounds__(256) void k_stageD1() {
    __shared__ ulonglong2 sTP[128];
    extern __shared__ __align__(16) u64 ddsm[];   // sG: 32 r x 32 c
    u64* sG = ddsm;

    int ky = blockIdx.x, b = blockIdx.y, ch = blockIdx.z;
    int tid = threadIdx.x;

    const u64* gsrc = g_G + ((size_t)(b*MY + ky)*32)*CC + ch*32;
    {
        unsigned sb = sptr(sG);
#pragma unroll
        for (int t = 0; t < 2; t++) {
            int idx = tid + t*256;            // 0..511
            int r = idx >> 4, q = idx & 15;   // row r (0..31), 16B chunk q (0..15)
            CP16(sb + r*256 + q*16, (const float*)(gsrc + (size_t)r*CC) + q*4);
        }
        asm volatile("cp.async.commit_group;");
    }
    for (int i = tid; i < 128; i += 256) sTP[i] = g_TP[i];
    asm volatile("cp.async.wait_group 0;");
    __syncthreads();

    int c2 = tid & 31;
    int c  = ch*32 + c2;
    int hg = tid >> 5;          // 0..7
    int hbase = 1 + hg*8;

    u64 mc[8], ms[8];
#pragma unroll
    for (int q = 0; q < 8; q++) { mc[q] = 0ull; ms[q] = 0ull; }
    u64 g0 = sG[c2];
    u64 Ssum = 0ull;

#pragma unroll
    for (int r = 1; r <= 16; r++) {
        u64 S, Dp;
        if (r < 16) {
            float2 ga = upk(sG[r*32 + c2]);
            float2 gb = upk(sG[(32 - r)*32 + c2]);
            S  = pk(ga.x + gb.x, ga.y + gb.y);
            Dp = pk(gb.y - ga.y, ga.x - gb.x);
        } else {
            float2 g = upk(sG[16*32 + c2]);
            S  = pk(g.x, g.y);
            Dp = pk(g.y, -g.x);
        }
        if (hg == 0) add2(Ssum, S);
        int mm = (r * hbase) & 127;
#pragma unroll
        for (int hh = 0; hh < 8; hh++) {
            ulonglong2 t = sTP[mm];
            fma2(mc[hh], S,  t.x);
            fma2(ms[hh], Dp, t.y);
            mm = (mm + r) & 127;
        }
    }

    float2 fg0 = upk(g0);
    size_t base = (size_t)(b*MY + ky)*HH;
#pragma unroll
    for (int hh = 0; hh < 8; hh++) {
        int h = hbase + hh;
        float2 cc = upk(mc[hh]), s2 = upk(ms[hh]);
        float tre = fg0.x + cc.x, tim = fg0.y + cc.y;
        size_t off = (base + h)*CC + c;
        g_Mre[off] = tre + s2.x;
        g_Mim[off] = tim + s2.y;
        if (h < 64) {
            size_t off2 = (base + 128 - h)*CC + c;
            g_Mre[off2] = tre - s2.x;
            g_Mim[off2] = tim - s2.y;
        }
    }
    if (hg == 0) {
        float2 fs = upk(Ssum);
        size_t off = base*CC + c;
        g_Mre[off] = fg0.x + fs.x;
        g_Mim[off] = fg0.y + fs.y;
    }
}

// ---------------- stage E: full-row cp.async staging + 2-chain dense/spectral + GELU ----------------
__global__ __launch_bounds__(256, 2) void k_stageE(const float* __restrict__ x,
                                                   const float* __restrict__ Kd,
                                                   const float* __restrict__ bias,
                                                   float* __restrict__ out) {
    extern __shared__ __align__(16) u64 dsm[];
    u64* xs2 = dsm;              // 4096 u64
    u64* sTC = dsm + 4096;       // 1024 u64
    u64* sTS = sTC + 1024;       // 1024 u64

    int h = blockIdx.x, b = blockIdx.y;
    int tid = threadIdx.x;
    int c  = tid & 63;
    int wg = tid >> 6;

    const float* xrow = x   + ((size_t)(b*HH + h)*WW)*CC;
    float*       orow = out + ((size_t)(b*HH + h)*WW)*CC;

    {
        unsigned sx = sptr(xs2);
#pragma unroll
        for (int j = 0; j < 8; j++) {
            int i = tid + j*256;
            CP16(sx + i*16, xrow + i*4);
        }
        unsigned stc = sptr(sTC), sts = sptr(sTS);
#pragma unroll
        for (int j = 0; j < 2; j++) {
            int i = tid + j*256;
            CP16(stc + i*16, (const float*)g_TC2 + i*4);
            CP16(sts + i*16, (const float*)g_TS2 + i*4);
        }
        asm volatile("cp.async.commit_group;");
    }

    u64 Kp[32];
#pragma unroll
    for (int i = 0; i < 32; i++)
        Kp[i] = pk(Kd[(2*i)*64 + c], Kd[(2*i+1)*64 + c]);

    u64 R2[8], I2[8];
#pragma unroll
    for (int j = 0; j < 8; j++) {
        size_t o0 = ((size_t)(b*MY + 2*j    )*HH + h)*CC + c;
        size_t o1 = ((size_t)(b*MY + 2*j + 1)*HH + h)*CC + c;
        R2[j] = pk(g_Mre[o0], g_Mre[o1]);
        I2[j] = pk(g_Mim[o0], g_Mim[o1]);
    }
    float bc = bias[c];

    asm volatile("cp.async.wait_group 0;");
    __syncthreads();

    for (int ww = 0; ww < 32; ww++) {
        int w = wg*32 + ww;
        u64 acc0 = pk(bc, 0.f);
        u64 acc1 = 0ull;
        const ulonglong2* xv = (const ulonglong2*)&xs2[w*32];
#pragma unroll
        for (int t = 0; t < 16; t++) {
            ulonglong2 q = xv[t];
            fma2(acc0, q.x, Kp[2*t]);
            fma2(acc1, q.y, Kp[2*t + 1]);
        }
        const ulonglong2* tcp = (const ulonglong2*)&sTC[w*8];
        const ulonglong2* tsp = (const ulonglong2*)&sTS[w*8];
#pragma unroll
        for (int t = 0; t < 4; t++) {
            ulonglong2 tc = tcp[t];
            ulonglong2 ts = tsp[t];
            fma2(acc0, R2[2*t],     tc.x);
            fma2(acc1, R2[2*t + 1], tc.y);
            fma2(acc0, I2[2*t],     ts.x);
            fma2(acc1, I2[2*t + 1], ts.y);
        }
        float2 s0 = upk(acc0), s1 = upk(acc1);
        float xval = ((const float*)xs2)[w*64 + c];
        float u = xval + s0.x + s0.y + s1.x + s1.y;
        float u3 = u*u*u;
        float t = fast_tanh(0.7978845608028654f*(u + 0.044715f*u3));
        orow[(size_t)w*64 + c] = 0.5f*u*(1.f + t);
    }
}

// ---------------- launch ----------------
extern "C" void kernel_launch(void* const* d_in, const int* in_sizes, int n_in,
                              void* d_out, int out_size) {
    const float* x    = (const float*)d_in[0];
    const float* w1r  = (const float*)d_in[1];
    const float* w1i  = (const float*)d_in[2];
    const float* w2r  = (const float*)d_in[3];
    const float* w2i  = (const float*)d_in[4];
    const float* Kd   = (const float*)d_in[5];
    const float* bias = (const float*)d_in[6];
    float* out = (float*)d_out;

    const int A_SMEM = 1152*8 + 2*8192*4;                   // 74752 bytes
    const int B_SMEM = 2*2048*8;                            // 32768 bytes
    const int C_SMEM = (4096 + 4096 + 64*20 + 64*20) * 4;   // 43008 bytes
    const int D_SMEM = 32*32*8;                             // 8192 bytes
    const int E_SMEM = (4096 + 1024 + 1024) * 8;            // 49152 bytes
    static int attr_set = 0;
    if (!attr_set) {
        cudaFuncSetAttribute(k_stageA, cudaFuncAttributeMaxDynamicSharedMemorySize, A_SMEM);
        cudaFuncSetAttribute(k_stageB, cudaFuncAttributeMaxDynamicSharedMemorySize, B_SMEM);
        cudaFuncSetAttribute(k_stageC, cudaFuncAttributeMaxDynamicSharedMemorySize, C_SMEM);
        cudaFuncSetAttribute(k_stageE, cudaFuncAttributeMaxDynamicSharedMemorySize, E_SMEM);
        attr_set = 1;
    }

    k_init<<<64, 256>>>();
    k_stageA<<<dim3(32, 32), 256, A_SMEM>>>(x);
    k_stageB<<<dim3(17, 32), 256, B_SMEM>>>();
    k_stageC<<<dim3(16, 32, 2), 256, C_SMEM>>>(w1r, w1i, w2r, w2i);
    k_stageD1<<<dim3(16, 32, 2), 256, D_SMEM>>>();
    k_stageE<<<dim3(128, 32), 256, E_SMEM>>>(x, Kd, bias, out);
}